// round 13
// baseline (speedup 1.0000x reference)
#include <cuda_runtime.h>
#include <cuda_bf16.h>
#include <cuda_fp16.h>
#include <math.h>
#include <stdint.h>

#define DX 512
#define DU 256
#define DOUT 256
#define DK 768
#define NB 16
#define SEQL 4096
#define CW 64           // warmup length
#define SCN_NCH 56      // chunks (56*74 = 4144 >= 4096)
#define SCN_CTS 74      // chunk length
#define OUT_ELEMS (NB*SEQL*DOUT)           /* 16777216 */
#define ST_ELEMS  ((size_t)NB*(SEQL+1)*DX) /* 33562624 */

// ---------------- device scratch (static; no runtime allocation) ----------------
__device__ float g_M0[DK*DK];
__device__ float g_M1[DK*DK];
__device__ float g_Xa[DX*DX];
__device__ float g_Xb[DX*DX];
__device__ float g_P[DX*DX];
__device__ float g_T1[DX*DX];
__device__ float g_Amat[DX*DX];
__device__ __half g_Apk[DX*DX];      // A in mma B-fragment layout, fp16
__device__ float g_Bm[DX*DU];
__device__ float g_E[DOUT*DK];
__device__ float g_Bu[(size_t)NB*SEQL*DX];
__device__ float g_states_fallback[(size_t)NB*(SEQL+1)*DX];
__device__ float g_part[64];
__device__ float g_tr[8];            // per-squaring trace accumulators
__device__ float g_kscale;

// bf16 split buffers. A-side layout [h,l,h]; B-side layout [h,h,l].
__device__ __nv_bfloat16 c_big1[(size_t)65536*1536]; // states3 (A-side)
__device__ __nv_bfloat16 c_big2[(size_t)65536*768];  // u3 (A-side)
__device__ __nv_bfloat16 c_kt[DK*2304];              // A-side DK
__device__ __nv_bfloat16 c_m [DK*2304];              // B-side DK
__device__ __nv_bfloat16 c_s [DX*1536];
__device__ __nv_bfloat16 c_st[DX*1536];
__device__ __nv_bfloat16 c_w1[DX*1536];
__device__ __nv_bfloat16 c_w2[DX*1536];
__device__ __nv_bfloat16 c_w3[DX*1536];
__device__ __nv_bfloat16 c_w4[DX*1536];
__device__ __nv_bfloat16 c_bm[DX*768];
__device__ __nv_bfloat16 c_dw[DOUT*768];

// ---------------- small kernels ----------------
__global__ void init_kernel() {
    int idx = blockIdx.x * blockDim.x + threadIdx.x;
    if (idx < 8) g_tr[idx] = 0.f;
    if (idx < DX*DX) {
        int i = idx / DX, j = idx - i*DX;
        g_Xa[idx] = (i == j) ? 1.f : 0.f;
    }
}

// Frobenius: tr(M^2) = ||M||_F^2 — stage 1: 64 partial sums
__global__ void frob_part(const float* __restrict__ M) {
    __shared__ float red[256];
    int tid = threadIdx.x;
    float s = 0.f;
    for (int i = blockIdx.x*256 + tid; i < DK*DK; i += 64*256) {
        float v = M[i]; s += v*v;
    }
    red[tid] = s; __syncthreads();
    for (int o = 128; o > 0; o >>= 1) {
        if (tid < o) red[tid] += red[tid+o];
        __syncthreads();
    }
    if (tid == 0) g_part[blockIdx.x] = red[0];
}

// L = sum_{i=0..6} 2^-i log(tr_i) + 2^-8 log(frob(M_7));  sigma = exp(L/2)
__global__ void finalize_kernel() {
    if (threadIdx.x != 0) return;
    double L = 0.0, w = 1.0;
    for (int i = 0; i < 7; ++i) {
        L += w * log((double)g_tr[i]);
        w *= 0.5;
    }
    float fb = 0.f;
    for (int i = 0; i < 64; ++i) fb += g_part[i];
    L += (w * 0.5) * log((double)fb);   // w = 2^-7 -> frob weight 2^-8
    float sigma = (float)exp(0.5 * L);
    if (sigma < 1e-5f) sigma = 1e-5f;
    g_kscale = 1.f / (sigma + 0.002f);
}

// pack A (fp32, row n x col h) -> fp16 fragments for mma m16n8k16 B operand.
__global__ void pack_frag_kernel() {
    int idx = blockIdx.x * blockDim.x + threadIdx.x;   // 262144
    int i = idx & 7, lane = (idx >> 3) & 31, ktp = (idx >> 8) & 15, nt = idx >> 12;
    int t = i >> 2, j = i & 3;
    int tig = lane & 3, gid = lane >> 2;
    int k = tig*2 + (j & 1) + ((j >> 1) * 8);
    int h = (2*ktp + t)*16 + k;
    int n = nt*8 + gid;
    g_Apk[idx] = __float2half(g_Amat[(size_t)n*DX + h]);
}

__global__ void dcopy_kernel(const float* __restrict__ Kraw) {
    int idx = blockIdx.x * blockDim.x + threadIdx.x;   // DOUT*DU
    int o = idx >> 8, h = idx & 255;
    g_E[(size_t)o*DK + DX + h] = g_kscale * Kraw[(size_t)(DX+o)*DK + DX + h];
}

__global__ void state0_kernel(const float* __restrict__ st, float* __restrict__ states) {
    int idx = blockIdx.x * blockDim.x + threadIdx.x;   // NB*DX
    int b = idx >> 9, n = idx & 511;
    states[(size_t)b*(SEQL+1)*DX + n] = st[idx];
}

// ---------------- fp32 -> bf16 3-term split, generic gather ----------------
__global__ void split3_kernel(const float* __restrict__ src, __nv_bfloat16* __restrict__ dst,
                              long long rs, long long cs, int K, long long total,
                              int rpb, long long bstr, int bmode)
{
    long long idx = (long long)blockIdx.x * 256 + threadIdx.x;
    if (idx >= total) return;
    long long r = idx / K;
    int k = (int)(idx - r * K);
    long long so;
    if (rpb > 0) { long long b = r / rpb, rr = r - b*rpb; so = b*bstr + rr*rs + (long long)k*cs; }
    else so = r*rs + (long long)k*cs;
    float x = src[so];
    __nv_bfloat16 h = __float2bfloat16(x);
    __nv_bfloat16 l = __float2bfloat16(x - __bfloat162float(h));
    __nv_bfloat16* d = dst + r*(3LL*K);
    if (bmode) { d[k] = h; d[K+k] = h; d[2*K+k] = l; }
    else       { d[k] = h; d[K+k] = l; d[2*K+k] = h; }
}

// dual: writes A-side AND B-side layouts; optionally accumulates trace into g_tr[slot]
__global__ void split3_dual_kernel(const float* __restrict__ src,
                                   __nv_bfloat16* __restrict__ dstA,
                                   __nv_bfloat16* __restrict__ dstB,
                                   long long rs, long long cs, int K, long long total,
                                   int tr_slot)
{
    long long idx = (long long)blockIdx.x * 256 + threadIdx.x;
    if (idx >= total) return;
    long long r = idx / K;
    int k = (int)(idx - r * K);
    float x = src[r*rs + (long long)k*cs];
    if (tr_slot >= 0 && (long long)k == r) atomicAdd(&g_tr[tr_slot], x);
    __nv_bfloat16 h = __float2bfloat16(x);
    __nv_bfloat16 l = __float2bfloat16(x - __bfloat162float(h));
    __nv_bfloat16* dA = dstA + r*(3LL*K);
    __nv_bfloat16* dB = dstB + r*(3LL*K);
    dA[k] = h; dA[K+k] = l; dA[2*K+k] = h;
    dB[k] = h; dB[K+k] = h; dB[2*K+k] = l;
}

// ---------------- tensor-core bf16-split GEMM (mma.sync, 3-stage pipeline) ----------------
__device__ __forceinline__ void cpa16(uint32_t s, const void* g) {
    asm volatile("cp.async.cg.shared.global [%0], [%1], 16;" :: "r"(s), "l"(g));
}
__device__ __forceinline__ void ldm4(uint32_t* f, uint32_t addr) {
    asm volatile("ldmatrix.sync.aligned.m8n8.x4.shared.b16 {%0,%1,%2,%3}, [%4];"
                 : "=r"(f[0]), "=r"(f[1]), "=r"(f[2]), "=r"(f[3]) : "r"(addr));
}
__device__ __forceinline__ void mma16816(float* c, const uint32_t* a, uint32_t b0, uint32_t b1) {
    asm volatile("mma.sync.aligned.m16n8k16.row.col.f32.bf16.bf16.f32 "
                 "{%0,%1,%2,%3}, {%4,%5,%6,%7}, {%8,%9}, {%0,%1,%2,%3};"
                 : "+f"(c[0]), "+f"(c[1]), "+f"(c[2]), "+f"(c[3])
                 : "r"(a[0]), "r"(a[1]), "r"(a[2]), "r"(a[3]), "r"(b0), "r"(b1));
}
__device__ __forceinline__ void mmaf16(float* c, const uint32_t* a, uint32_t b0, uint32_t b1) {
    asm volatile("mma.sync.aligned.m16n8k16.row.col.f32.f16.f16.f32 "
                 "{%0,%1,%2,%3}, {%4,%5,%6,%7}, {%8,%9}, {%0,%1,%2,%3};"
                 : "+f"(c[0]), "+f"(c[1]), "+f"(c[2]), "+f"(c[3])
                 : "r"(a[0]), "r"(a[1]), "r"(a[2]), "r"(a[3]), "r"(b0), "r"(b1));
}
#define SWZ(x) ((x) ^ (((x) >> 3) & 0x70))

template<int MT, int WN>
__global__ __launch_bounds__(WN*64)
void tc_gemm(const __nv_bfloat16* __restrict__ A3, const __nv_bfloat16* __restrict__ B3,
             const float* __restrict__ Dm, float* __restrict__ C,
             int K3, int ldd, int ldc, int amode, float alpha, float beta, int tridx)
{
    constexpr int BM = MT*32;
    constexpr int BN = WN*32;
    constexpr int THREADS = WN*64;
    constexpr uint32_t ABYTES = BM*128;
    constexpr uint32_t BBYTES = BN*128;
    constexpr uint32_t STAGE = ABYTES + BBYTES;

    extern __shared__ char smem[];
    uint32_t sbase = (uint32_t)__cvta_generic_to_shared(smem);

    int tid = threadIdx.x;
    int wid = tid >> 5, lane = tid & 31;
    int wm = wid & 1, wn = wid >> 1;
    int m0 = blockIdx.y * BM, n0 = blockIdx.x * BN;

    int q = lane >> 3, r = lane & 7;
    uint32_t aRow[MT], aXor[MT];
    #pragma unroll
    for (int mt = 0; mt < MT; ++mt) {
        int row = wm*(MT*16) + mt*16 + (q & 1)*8 + r;
        aRow[mt] = (uint32_t)row * 128;
        aXor[mt] = (uint32_t)(row & 7) * 16;
    }
    uint32_t aCsel = (uint32_t)(q >> 1) * 16;
    uint32_t bRow[2], bXor[2];
    #pragma unroll
    for (int p = 0; p < 2; ++p) {
        int row = wn*32 + (2*p + (q >> 1))*8 + r;
        bRow[p] = (uint32_t)row * 128;
        bXor[p] = (uint32_t)(row & 7) * 16;
    }
    uint32_t bCsel = (uint32_t)(q & 1) * 16;

    float acc[MT][4][4];
    #pragma unroll
    for (int i = 0; i < MT; ++i)
        #pragma unroll
        for (int j = 0; j < 4; ++j)
            #pragma unroll
            for (int v = 0; v < 4; ++v) acc[i][j][v] = 0.f;

    int nk = K3 >> 6;

    auto load_tile = [&](int j, int stg) {
        int kt = j << 6;
        uint32_t sA = sbase + (uint32_t)stg*STAGE;
        uint32_t sB = sA + ABYTES;
        #pragma unroll
        for (int i = 0; i < (BM*8)/THREADS; ++i) {
            int c = tid + i*THREADS;
            int row = c >> 3, col16 = c & 7;
            uint32_t off = (uint32_t)(row*128 + col16*16);
            cpa16(sA + SWZ(off), A3 + (size_t)(m0+row)*K3 + kt + col16*8);
        }
        #pragma unroll
        for (int i = 0; i < (BN*8)/THREADS; ++i) {
            int c = tid + i*THREADS;
            int row = c >> 3, col16 = c & 7;
            uint32_t off = (uint32_t)(row*128 + col16*16);
            cpa16(sB + SWZ(off), B3 + (size_t)(n0+row)*K3 + kt + col16*8);
        }
        asm volatile("cp.async.commit_group;" ::: "memory");
    };

    load_tile(0, 0);
    if (nk > 1) load_tile(1, 1);

    for (int ki = 0; ki < nk; ++ki) {
        int stg = ki % 3;
        if (ki + 2 < nk) {
            load_tile(ki + 2, (ki + 2) % 3);
            asm volatile("cp.async.wait_group 2;" ::: "memory");
        } else if (ki + 1 < nk) {
            asm volatile("cp.async.wait_group 1;" ::: "memory");
        } else {
            asm volatile("cp.async.wait_group 0;" ::: "memory");
        }
        __syncthreads();

        uint32_t sA = sbase + (uint32_t)stg*STAGE;
        uint32_t sB = sA + ABYTES;
        #pragma unroll
        for (int kk = 0; kk < 4; ++kk) {
            uint32_t afr[MT][4];
            #pragma unroll
            for (int mt = 0; mt < MT; ++mt)
                ldm4(afr[mt], sA + aRow[mt] + (((uint32_t)(kk*32) + aCsel) ^ aXor[mt]));
            uint32_t bfr[2][4];
            #pragma unroll
            for (int p = 0; p < 2; ++p)
                ldm4(bfr[p], sB + bRow[p] + (((uint32_t)(kk*32) + bCsel) ^ bXor[p]));
            #pragma unroll
            for (int mt = 0; mt < MT; ++mt)
                #pragma unroll
                for (int nt = 0; nt < 4; ++nt)
                    mma16816(acc[mt][nt], afr[mt], bfr[nt >> 1][(nt & 1)*2], bfr[nt >> 1][(nt & 1)*2 + 1]);
        }
        __syncthreads();
    }

    float mult = alpha;
    if (amode == 1) { float t = g_tr[tridx]; mult = alpha / (t * t); }
    else if (amode == 2) mult *= g_kscale;

    int cr = lane >> 2, cc = (lane & 3) * 2;
    #pragma unroll
    for (int mt = 0; mt < MT; ++mt) {
        #pragma unroll
        for (int nt = 0; nt < 4; ++nt) {
            int gm = m0 + wm*(MT*16) + mt*16 + cr;
            int gn = n0 + wn*32 + nt*8 + cc;
            float2 v0, v1;
            v0.x = mult*acc[mt][nt][0]; v0.y = mult*acc[mt][nt][1];
            v1.x = mult*acc[mt][nt][2]; v1.y = mult*acc[mt][nt][3];
            if (beta != 0.f) {
                float2 d0 = *(const float2*)&Dm[(size_t)gm*ldd + gn];
                float2 d1 = *(const float2*)&Dm[(size_t)(gm+8)*ldd + gn];
                v0.x += beta*d0.x; v0.y += beta*d0.y;
                v1.x += beta*d1.x; v1.y += beta*d1.y;
            }
            *(float2*)&C[(size_t)gm*ldc + gn] = v0;
            *(float2*)&C[(size_t)(gm+8)*ldc + gn] = v1;
        }
    }
}

// ---------------- scan via mma.sync fp16 ----------------
// grid = 56 CTAs (one chunk each, all 16 batches), 256 threads = 8 warps.
#define XPITCH_B 1040u            /* bytes per x row (512*2 + 16 pad) */
#define HLBYTES  (16u*XPITCH_B)   /* one h or l section: 16640 B */
#define BUFBYTES (2u*HLBYTES)     /* h + l: 33280 B */
#define SCN_SMEM (2u*BUFBYTES)    /* double buffer: 66560 B */

__global__ __launch_bounds__(256)
void scan_mma_kernel(const float* __restrict__ Bu, const __half* __restrict__ Apk,
                     const float* __restrict__ state0, float* __restrict__ states)
{
    extern __shared__ char sm[];
    uint32_t sbase = (uint32_t)__cvta_generic_to_shared(sm);
    int tid = threadIdx.x, wid = tid >> 5, lane = tid & 31;
    int gid = lane >> 2, tig = lane & 3;
    int q = lane >> 3, rr = lane & 7;
    uint32_t lrow = (uint32_t)((q & 1)*8 + rr) * XPITCH_B;
    uint32_t lcs  = (uint32_t)(q >> 1) * 16;

    int c = blockIdx.x;
    int t0 = c * SCN_CTS;
    int tend = t0 + SCN_CTS; if (tend > SEQL) tend = SEQL;
    int tstart = t0 - CW; if (tstart < 0) tstart = 0;
    bool fromstate = (tstart == 0);

    for (int i = tid; i < 16*512; i += 256) {
        int m = i >> 9, n = i & 511;
        float v = fromstate ? state0[(size_t)m*DX + n] : 0.f;
        __half h = __float2half(v);
        __half l = __float2half(v - __half2float(h));
        *(__half*)(sm + m*XPITCH_B + n*2) = h;
        *(__half*)(sm + HLBYTES + m*XPITCH_B + n*2) = l;
    }
    __syncthreads();

    int nbase = wid * 64;
    int buf = 0;

    for (int t = tstart; t < tend; ++t) {
        float acc[8][4];
        {
            const float* bu0 = Bu + ((size_t)gid*SEQL + t)*DX;
            const float* bu1 = Bu + ((size_t)(gid+8)*SEQL + t)*DX;
            #pragma unroll
            for (int nt = 0; nt < 8; ++nt) {
                int n = nbase + nt*8 + tig*2;
                float2 v0 = *(const float2*)(bu0 + n);
                float2 v1 = *(const float2*)(bu1 + n);
                acc[nt][0] = v0.x; acc[nt][1] = v0.y;
                acc[nt][2] = v1.x; acc[nt][3] = v1.y;
            }
        }
        uint32_t bh = sbase + (uint32_t)buf*BUFBYTES;
        uint32_t bl = bh + HLBYTES;

        #pragma unroll 2
        for (int ktp = 0; ktp < 16; ++ktp) {
            uint32_t afh0[4], afh1[4], afl0[4], afl1[4];
            uint32_t cb = (uint32_t)(ktp*64);
            ldm4(afh0, bh + lrow + cb + lcs);
            ldm4(afh1, bh + lrow + cb + 32 + lcs);
            ldm4(afl0, bl + lrow + cb + lcs);
            ldm4(afl1, bl + lrow + cb + 32 + lcs);
            #pragma unroll
            for (int nt = 0; nt < 8; ++nt) {
                uint4 bv = *(const uint4*)(Apk +
                    ((((size_t)(wid*8 + nt)*16 + ktp)*32 + lane) << 3));
                mmaf16(acc[nt], afh0, bv.x, bv.y);
                mmaf16(acc[nt], afh1, bv.z, bv.w);
                mmaf16(acc[nt], afl0, bv.x, bv.y);
                mmaf16(acc[nt], afl1, bv.z, bv.w);
            }
        }

        char* nb = sm + (buf ^ 1)*BUFBYTES;
        bool wr = (t >= t0);
        float* st0 = states + ((size_t)gid*(SEQL+1) + (t+1))*DX;
        float* st1 = states + ((size_t)(gid+8)*(SEQL+1) + (t+1))*DX;
        #pragma unroll
        for (int nt = 0; nt < 8; ++nt) {
            int n = nbase + nt*8 + tig*2;
            float v0 = acc[nt][0], v1 = acc[nt][1];
            float v2 = acc[nt][2], v3 = acc[nt][3];
            __half h0 = __float2half(v0), h1 = __float2half(v1);
            __half h2 = __float2half(v2), h3 = __float2half(v3);
            __half l0 = __float2half(v0 - __half2float(h0));
            __half l1 = __float2half(v1 - __half2float(h1));
            __half l2 = __float2half(v2 - __half2float(h2));
            __half l3 = __float2half(v3 - __half2float(h3));
            *(__half2*)(nb + gid*XPITCH_B + n*2)                    = __halves2half2(h0, h1);
            *(__half2*)(nb + (gid+8)*XPITCH_B + n*2)                = __halves2half2(h2, h3);
            *(__half2*)(nb + HLBYTES + gid*XPITCH_B + n*2)          = __halves2half2(l0, l1);
            *(__half2*)(nb + HLBYTES + (gid+8)*XPITCH_B + n*2)      = __halves2half2(l2, l3);
            if (wr) {
                *(float2*)(st0 + n) = make_float2(v0, v1);
                *(float2*)(st1 + n) = make_float2(v2, v3);
            }
        }
        __syncthreads();
        buf ^= 1;
    }
}

// ---------------- host ----------------
static void* symaddr(const void* sym) {
    void* p = nullptr;
    cudaGetSymbolAddress(&p, sym);
    return p;
}

static void SPLIT(const float* src, __nv_bfloat16* dst, long long rs, long long cs,
                  int K, long long rows, int bmode, int rpb = 0, long long bstr = 0)
{
    long long total = rows * (long long)K;
    int grid = (int)((total + 255) / 256);
    split3_kernel<<<grid, 256>>>(src, dst, rs, cs, K, total, rpb, bstr, bmode);
}

static void SPLITD(const float* src, __nv_bfloat16* dstA, __nv_bfloat16* dstB,
                   long long rs, long long cs, int K, long long rows, int tr_slot)
{
    long long total = rows * (long long)K;
    int grid = (int)((total + 255) / 256);
    split3_dual_kernel<<<grid, 256>>>(src, dstA, dstB, rs, cs, K, total, tr_slot);
}

static void TCG(const __nv_bfloat16* A3, const __nv_bfloat16* B3, const float* Dm, float* Cp,
                int M, int N, int K3, int ldd, int ldc, int amode, float alpha, float beta,
                int tridx = 0)
{
    if (M >= 1024) {
        dim3 g(N/128, M/128);
        tc_gemm<4,4><<<g, 256, 98304>>>(A3, B3, Dm, Cp, K3, ldd, ldc, amode, alpha, beta, tridx);
    } else {
        dim3 g(N/64, M/64);
        tc_gemm<2,2><<<g, 128, 49152>>>(A3, B3, Dm, Cp, K3, ldd, ldc, amode, alpha, beta, tridx);
    }
}

extern "C" void kernel_launch(void* const* d_in, const int* in_sizes, int n_in,
                              void* d_out, int out_size)
{
    const float *u = nullptr, *state = nullptr, *S = nullptr, *Kraw = nullptr;
    for (int i = 0; i < n_in; ++i) {
        long long sz = in_sizes[i];
        if      (sz == (long long)NB*SEQL*DU) u     = (const float*)d_in[i];
        else if (sz == (long long)NB*DX)      state = (const float*)d_in[i];
        else if (sz == (long long)DX*DX)      S     = (const float*)d_in[i];
        else if (sz == (long long)DK*DK)      Kraw  = (const float*)d_in[i];
    }
    float* out = (float*)d_out;

    cudaFuncSetAttribute((const void*)tc_gemm<4,4>, cudaFuncAttributeMaxDynamicSharedMemorySize, 98304);
    cudaFuncSetAttribute((const void*)tc_gemm<2,2>, cudaFuncAttributeMaxDynamicSharedMemorySize, 49152);
    cudaFuncSetAttribute((const void*)scan_mma_kernel, cudaFuncAttributeMaxDynamicSharedMemorySize, SCN_SMEM);

    float* pM0    = (float*)symaddr(g_M0);
    float* pM1    = (float*)symaddr(g_M1);
    float* pXa    = (float*)symaddr(g_Xa);
    float* pXb    = (float*)symaddr(g_Xb);
    float* pP     = (float*)symaddr(g_P);
    float* pT1    = (float*)symaddr(g_T1);
    float* pAmat  = (float*)symaddr(g_Amat);
    float* pBm    = (float*)symaddr(g_Bm);
    float* pE     = (float*)symaddr(g_E);
    float* pBu    = (float*)symaddr(g_Bu);
    float* pFall  = (float*)symaddr(g_states_fallback);
    __half* pApk  = (__half*)symaddr(g_Apk);

    __nv_bfloat16* pcBig1 = (__nv_bfloat16*)symaddr(c_big1);
    __nv_bfloat16* pcBig2 = (__nv_bfloat16*)symaddr(c_big2);
    __nv_bfloat16* pcKT   = (__nv_bfloat16*)symaddr(c_kt);
    __nv_bfloat16* pcM    = (__nv_bfloat16*)symaddr(c_m);
    __nv_bfloat16* pcS    = (__nv_bfloat16*)symaddr(c_s);
    __nv_bfloat16* pcST   = (__nv_bfloat16*)symaddr(c_st);
    __nv_bfloat16* pcW1   = (__nv_bfloat16*)symaddr(c_w1);
    __nv_bfloat16* pcW2   = (__nv_bfloat16*)symaddr(c_w2);
    __nv_bfloat16* pcW3   = (__nv_bfloat16*)symaddr(c_w3);
    __nv_bfloat16* pcW4   = (__nv_bfloat16*)symaddr(c_w4);
    __nv_bfloat16* pcBm   = (__nv_bfloat16*)symaddr(c_bm);
    __nv_bfloat16* pcDw   = (__nv_bfloat16*)symaddr(c_dw);

    float* states = ((long long)out_size >= (long long)OUT_ELEMS + (long long)ST_ELEMS)
                    ? (out + OUT_ELEMS) : pFall;

    // --- init (g_tr=0, X0=I) ---
    init_kernel<<<(DX*DX + 255)/256, 256>>>();

    // --- sigma: M0 = K^T K, 7 trace-normalized squarings (trace fused into split),
    //     Frobenius finish. Estimator exponent 256; eigengap residual ~6e-6. ---
    SPLITD(Kraw, pcKT, pcM, 1, DK, DK, DK, -1);             // K^T, both sides
    TCG(pcKT, pcM, nullptr, pM0, DK, DK, 3*DK, 0, DK, 0, 1.f, 0.f);
    float* Ms[2] = {pM0, pM1};
    for (int i = 0; i < 7; ++i) {
        SPLITD(Ms[i & 1], pcKT, pcM, DK, 1, DK, DK, i);     // split + tr(M_i) -> g_tr[i]
        TCG(pcKT, pcM, nullptr, Ms[(i+1) & 1], DK, DK, 3*DK, 0, DK, 1, 1.f, 0.f, i);
    }
    frob_part<<<64,256>>>(Ms[1]);                           // M_7 in buffer 1
    finalize_kernel<<<1,1>>>();

    // --- Sinv via Newton-Schulz: X <- 2X - X S X, 4 iters ---
    SPLIT(S, pcS, DX, 1, DX, DX, 0);                        // S rows, A-side (once)
    float* Xc = pXa; float* Xn = pXb;
    for (int it = 0; it < 4; ++it) {
        SPLIT(Xc, pcW1, DX, 1, DX, DX, 0);                  // Xc rows, A-side
        SPLIT(Xc, pcW2, 1, DX, DX, DX, 1);                  // Xc^T, B-side
        TCG(pcS, pcW2, nullptr, pP, DX, DX, 1536, 0, DX, 0, 1.f, 0.f);   // P = S@Xc
        SPLIT(pP, pcW3, 1, DX, DX, DX, 1);                  // P^T, B-side
        TCG(pcW1, pcW3, Xc, Xn, DX, DX, 1536, DX, DX, 0, -1.f, 2.f);     // Xn = 2Xc - Xc@P
        float* tmp = Xc; Xc = Xn; Xn = tmp;
    }
    // Xc == Sinv

    // --- assemble A, B, C, D (all carry kscale; GAMMA=1) ---
    SPLIT(Xc, pcW4, DX, 1, DX, DX, 0);                      // Sinv rows, A-side
    SPLIT(S, pcST, 1, DX, DX, DX, 1);                       // S^T, B-side
    SPLIT(Kraw, pcW1, DK, 1, DX, DX, 0);                    // K11 rows, A-side [512 x 512]
    TCG(pcW1, pcST, nullptr, pT1, DX, DX, 1536, 0, DX, 2, 1.f, 0.f);     // T1 = ks*K11@S
    SPLIT(pT1, pcW2, 1, DX, DX, DX, 1);                     // T1^T, B-side
    TCG(pcW4, pcW2, nullptr, pAmat, DX, DX, 1536, 0, DX, 0, 1.f, 0.f);   // A = Sinv@T1
    pack_frag_kernel<<<(DX*DX)/256, 256>>>();
    SPLIT(Kraw + DX, pcW3, 1, DK, DX, DU, 1);               // K12^T, B-side [256 x 512]
    TCG(pcW4, pcW3, nullptr, pBm, DX, DU, 1536, 0, DU, 2, 1.f, 0.f);     // B = ks*Sinv@K12
    SPLIT(Kraw + (size_t)DX*DK, pcW1, DK, 1, DX, DOUT, 0);  // K21 rows, A-side [256 x 512]
    TCG(pcW1, pcST, nullptr, pE, DOUT, DX, 1536, 0, DK, 2, 1.f, 0.f);    // C = ks*K21@S
    dcopy_kernel<<<(DOUT*DU)/256, 256>>>(Kraw);             // D block of E

    // --- Bu = u @ B^T  [65536 x 512] ---
    SPLIT(pBm, pcBm, DU, 1, DU, DX, 1);                     // Bm rows, B-side [512 x 256]
    SPLIT(u, pcBig2, DU, 1, DU, (long long)NB*SEQL, 0);     // u3, A-side [65536 x 768]
    TCG(pcBig2, pcBm, nullptr, pBu, NB*SEQL, DX, 768, 0, DX, 0, 1.f, 0.f);

    // --- scan (mma.sync fp16, 56 chunk CTAs) ---
    state0_kernel<<<(NB*DX)/256, 256>>>(state, states);
    scan_mma_kernel<<<SCN_NCH, 256, SCN_SMEM>>>(pBu, pApk, state, states);

    // --- output = pre_states @ C^T + u @ D^T ---
    SPLIT(pE, pcW2, DK, 1, DX, DOUT, 1);                    // Cw rows, B-side [256 x 512]
    SPLIT(pE + DX, pcDw, DK, 1, DU, DOUT, 1);               // Dw rows, B-side [256 x 256]
    SPLIT(states, pcBig1, DX, 1, DX, (long long)NB*SEQL, 0, SEQL, (long long)(SEQL+1)*DX);
    TCG(pcBig1, pcW2, nullptr, out, NB*SEQL, DOUT, 1536, 0, DOUT, 0, 1.f, 0.f);
    TCG(pcBig2, pcDw, out, out, NB*SEQL, DOUT, 768, DOUT, DOUT, 0, 1.f, 1.f);
}

// round 14
// speedup vs baseline: 1.4643x; 1.4643x over previous
#include <cuda_runtime.h>
#include <cuda_bf16.h>
#include <cuda_fp16.h>
#include <math.h>
#include <stdint.h>

#define DX 512
#define DU 256
#define DOUT 256
#define DK 768
#define NB 16
#define SEQL 4096
#define MCTS 14         // macro steps per chunk (147*14 = 2058 >= 2048)
#define MCW 28          // macro warmup (56 time-steps)
#define EO_NCH 147
#define OUT_ELEMS (NB*SEQL*DOUT)           /* 16777216 */
#define ST_ELEMS  ((size_t)NB*(SEQL+1)*DX) /* 33562624 */

// ---------------- device scratch (static; no runtime allocation) ----------------
__device__ float g_M0[DK*DK];
__device__ float g_M1[DK*DK];
__device__ float g_Xa[DX*DX];
__device__ float g_Xb[DX*DX];
__device__ float g_P[DX*DX];
__device__ float g_T1[DX*DX];
__device__ float g_Amat[DX*DX];
__device__ __half g_Apk[DX*DX];      // A^2 in mma B-fragment layout, fp16
__device__ float g_Bm[DX*DU];
__device__ float g_E[DOUT*DK];
__device__ float g_Bu[(size_t)NB*SEQL*DX];   // holds c_t = G u_t + B u_{t+1}
__device__ float g_X1[NB*DX];
__device__ float g_states_fallback[(size_t)NB*(SEQL+1)*DX];
__device__ float g_part[64];
__device__ float g_tr[8];            // per-squaring trace accumulators
__device__ float g_kscale;

// bf16 split buffers. A-side layout [h,l,h]; B-side layout [h,h,l].
__device__ __nv_bfloat16 c_big1[(size_t)65536*1536]; // u2 (pre-scan) / states3 (post-scan)
__device__ __nv_bfloat16 c_big2[(size_t)65536*768];  // u3 (A-side)
__device__ __nv_bfloat16 c_kt[DK*2304];              // A-side DK
__device__ __nv_bfloat16 c_m [DK*2304];              // B-side DK
__device__ __nv_bfloat16 c_s [DX*1536];
__device__ __nv_bfloat16 c_st[DX*1536];
__device__ __nv_bfloat16 c_w1[DX*1536];
__device__ __nv_bfloat16 c_w2[DX*1536];
__device__ __nv_bfloat16 c_w3[DX*1536];
__device__ __nv_bfloat16 c_w4[DX*1536];
__device__ __nv_bfloat16 c_dw[DOUT*768];

// ---------------- small kernels ----------------
__global__ void init_kernel() {
    int idx = blockIdx.x * blockDim.x + threadIdx.x;
    if (idx < 8) g_tr[idx] = 0.f;
    if (idx < DX*DX) {
        int i = idx / DX, j = idx - i*DX;
        g_Xa[idx] = (i == j) ? 1.f : 0.f;
    }
}

// Frobenius: tr(M^2) = ||M||_F^2 — stage 1: 64 partial sums
__global__ void frob_part(const float* __restrict__ M) {
    __shared__ float red[256];
    int tid = threadIdx.x;
    float s = 0.f;
    for (int i = blockIdx.x*256 + tid; i < DK*DK; i += 64*256) {
        float v = M[i]; s += v*v;
    }
    red[tid] = s; __syncthreads();
    for (int o = 128; o > 0; o >>= 1) {
        if (tid < o) red[tid] += red[tid+o];
        __syncthreads();
    }
    if (tid == 0) g_part[blockIdx.x] = red[0];
}

// L = sum_{i=0..7} 2^-i log(tr_i) + 2^-9 log(frob(M_8));  sigma = exp(L/2)
__global__ void finalize_kernel() {
    if (threadIdx.x != 0) return;
    double L = 0.0, w = 1.0;
    for (int i = 0; i < 8; ++i) {
        L += w * log((double)g_tr[i]);
        w *= 0.5;
    }
    float fb = 0.f;
    for (int i = 0; i < 64; ++i) fb += g_part[i];
    L += (w * 0.5) * log((double)fb);   // w = 2^-8 -> frob weight 2^-9
    float sigma = (float)exp(0.5 * L);
    if (sigma < 1e-5f) sigma = 1e-5f;
    g_kscale = 1.f / (sigma + 0.002f);
}

// pack src (fp32, row n x col h, 512x512) -> fp16 fragments for mma m16n8k16 B operand.
__global__ void pack_frag_kernel(const float* __restrict__ src) {
    int idx = blockIdx.x * blockDim.x + threadIdx.x;   // 262144
    int i = idx & 7, lane = (idx >> 3) & 31, ktp = (idx >> 8) & 15, nt = idx >> 12;
    int t = i >> 2, j = i & 3;
    int tig = lane & 3, gid = lane >> 2;
    int k = tig*2 + (j & 1) + ((j >> 1) * 8);
    int h = (2*ktp + t)*16 + k;
    int n = nt*8 + gid;
    g_Apk[idx] = __float2half(src[(size_t)n*DX + h]);
}

__global__ void dcopy_kernel(const float* __restrict__ Kraw) {
    int idx = blockIdx.x * blockDim.x + threadIdx.x;   // DOUT*DU
    int o = idx >> 8, h = idx & 255;
    g_E[(size_t)o*DK + DX + h] = g_kscale * Kraw[(size_t)(DX+o)*DK + DX + h];
}

__global__ void state0_kernel(const float* __restrict__ st, float* __restrict__ states) {
    int idx = blockIdx.x * blockDim.x + threadIdx.x;   // NB*DX
    int b = idx >> 9, n = idx & 511;
    states[(size_t)b*(SEQL+1)*DX + n] = st[idx];
}

// x1 = state0 @ A^T + Bm @ u_0  (exact fp32). Also writes states[.][1].
__global__ void x1_kernel(const float* __restrict__ state0, const float* __restrict__ u,
                          float* __restrict__ states) {
    __shared__ float s0[DX];
    __shared__ float u0[DU];
    int b = blockIdx.x, n = threadIdx.x;   // 512 threads
    s0[n] = state0[b*DX + n];
    if (n < DU) u0[n] = u[(size_t)b*SEQL*DU + n];
    __syncthreads();
    float acc = 0.f;
    const float* arow = g_Amat + (size_t)n*DX;
    for (int h = 0; h < DX; ++h) acc += arow[h] * s0[h];
    const float* brow = g_Bm + (size_t)n*DU;
    for (int h = 0; h < DU; ++h) acc += brow[h] * u0[h];
    g_X1[b*DX + n] = acc;
    states[((size_t)b*(SEQL+1) + 1)*DX + n] = acc;
}

// GBf[o][k] = k<256 ? G[o][k] : Bm[o][k-256]   (into g_Xb, 512x512)
__global__ void gb_kernel(const float* __restrict__ G) {
    int idx = blockIdx.x * blockDim.x + threadIdx.x;   // 512*512
    int o = idx >> 9, k = idx & 511;
    g_Xb[idx] = (k < DU) ? G[o*DU + k] : g_Bm[(size_t)o*DU + (k - DU)];
}

// ---------------- fp32 -> bf16 3-term split, generic gather ----------------
__global__ void split3_kernel(const float* __restrict__ src, __nv_bfloat16* __restrict__ dst,
                              long long rs, long long cs, int K, long long total,
                              int rpb, long long bstr, int bmode)
{
    long long idx = (long long)blockIdx.x * 256 + threadIdx.x;
    if (idx >= total) return;
    long long r = idx / K;
    int k = (int)(idx - r * K);
    long long so;
    if (rpb > 0) { long long b = r / rpb, rr = r - b*rpb; so = b*bstr + rr*rs + (long long)k*cs; }
    else so = r*rs + (long long)k*cs;
    float x = src[so];
    __nv_bfloat16 h = __float2bfloat16(x);
    __nv_bfloat16 l = __float2bfloat16(x - __bfloat162float(h));
    __nv_bfloat16* d = dst + r*(3LL*K);
    if (bmode) { d[k] = h; d[K+k] = h; d[2*K+k] = l; }
    else       { d[k] = h; d[K+k] = l; d[2*K+k] = h; }
}

// dual: writes A-side AND B-side layouts; optionally accumulates trace into g_tr[slot]
__global__ void split3_dual_kernel(const float* __restrict__ src,
                                   __nv_bfloat16* __restrict__ dstA,
                                   __nv_bfloat16* __restrict__ dstB,
                                   long long rs, long long cs, int K, long long total,
                                   int tr_slot)
{
    long long idx = (long long)blockIdx.x * 256 + threadIdx.x;
    if (idx >= total) return;
    long long r = idx / K;
    int k = (int)(idx - r * K);
    float x = src[r*rs + (long long)k*cs];
    if (tr_slot >= 0 && (long long)k == r) atomicAdd(&g_tr[tr_slot], x);
    __nv_bfloat16 h = __float2bfloat16(x);
    __nv_bfloat16 l = __float2bfloat16(x - __bfloat162float(h));
    __nv_bfloat16* dA = dstA + r*(3LL*K);
    __nv_bfloat16* dB = dstB + r*(3LL*K);
    dA[k] = h; dA[K+k] = l; dA[2*K+k] = h;
    dB[k] = h; dB[K+k] = h; dB[2*K+k] = l;
}

// u2[r=b*4096+t][k] = k<256 ? u[b][t][k] : (t+1<4096 ? u[b][t+1][k-256] : 0)  A-side split
__global__ void split3_u2_kernel(const float* __restrict__ u, __nv_bfloat16* __restrict__ dst)
{
    long long idx = (long long)blockIdx.x * 256 + threadIdx.x;   // 65536*512
    long long r = idx >> 9;
    int k = (int)(idx & 511);
    int b = (int)(r >> 12), t = (int)(r & 4095);
    float x;
    if (k < DU) x = u[((size_t)b*SEQL + t)*DU + k];
    else        x = (t + 1 < SEQL) ? u[((size_t)b*SEQL + t + 1)*DU + (k - DU)] : 0.f;
    __nv_bfloat16 h = __float2bfloat16(x);
    __nv_bfloat16 l = __float2bfloat16(x - __bfloat162float(h));
    __nv_bfloat16* d = dst + r*1536;
    d[k] = h; d[512+k] = l; d[1024+k] = h;
}

// ---------------- tensor-core bf16-split GEMM (mma.sync, 3-stage pipeline) ----------------
__device__ __forceinline__ void cpa16(uint32_t s, const void* g) {
    asm volatile("cp.async.cg.shared.global [%0], [%1], 16;" :: "r"(s), "l"(g));
}
__device__ __forceinline__ void ldm4(uint32_t* f, uint32_t addr) {
    asm volatile("ldmatrix.sync.aligned.m8n8.x4.shared.b16 {%0,%1,%2,%3}, [%4];"
                 : "=r"(f[0]), "=r"(f[1]), "=r"(f[2]), "=r"(f[3]) : "r"(addr));
}
__device__ __forceinline__ void mma16816(float* c, const uint32_t* a, uint32_t b0, uint32_t b1) {
    asm volatile("mma.sync.aligned.m16n8k16.row.col.f32.bf16.bf16.f32 "
                 "{%0,%1,%2,%3}, {%4,%5,%6,%7}, {%8,%9}, {%0,%1,%2,%3};"
                 : "+f"(c[0]), "+f"(c[1]), "+f"(c[2]), "+f"(c[3])
                 : "r"(a[0]), "r"(a[1]), "r"(a[2]), "r"(a[3]), "r"(b0), "r"(b1));
}
__device__ __forceinline__ void mmaf16(float* c, const uint32_t* a, uint32_t b0, uint32_t b1) {
    asm volatile("mma.sync.aligned.m16n8k16.row.col.f32.f16.f16.f32 "
                 "{%0,%1,%2,%3}, {%4,%5,%6,%7}, {%8,%9}, {%0,%1,%2,%3};"
                 : "+f"(c[0]), "+f"(c[1]), "+f"(c[2]), "+f"(c[3])
                 : "r"(a[0]), "r"(a[1]), "r"(a[2]), "r"(a[3]), "r"(b0), "r"(b1));
}
#define SWZ(x) ((x) ^ (((x) >> 3) & 0x70))

template<int MT, int WN>
__global__ __launch_bounds__(WN*64)
void tc_gemm(const __nv_bfloat16* __restrict__ A3, const __nv_bfloat16* __restrict__ B3,
             const float* __restrict__ Dm, float* __restrict__ C,
             int K3, int ldd, int ldc, int amode, float alpha, float beta, int tridx)
{
    constexpr int BM = MT*32;
    constexpr int BN = WN*32;
    constexpr int THREADS = WN*64;
    constexpr uint32_t ABYTES = BM*128;
    constexpr uint32_t BBYTES = BN*128;
    constexpr uint32_t STAGE = ABYTES + BBYTES;

    extern __shared__ char smem[];
    uint32_t sbase = (uint32_t)__cvta_generic_to_shared(smem);

    int tid = threadIdx.x;
    int wid = tid >> 5, lane = tid & 31;
    int wm = wid & 1, wn = wid >> 1;
    int m0 = blockIdx.y * BM, n0 = blockIdx.x * BN;

    int q = lane >> 3, r = lane & 7;
    uint32_t aRow[MT], aXor[MT];
    #pragma unroll
    for (int mt = 0; mt < MT; ++mt) {
        int row = wm*(MT*16) + mt*16 + (q & 1)*8 + r;
        aRow[mt] = (uint32_t)row * 128;
        aXor[mt] = (uint32_t)(row & 7) * 16;
    }
    uint32_t aCsel = (uint32_t)(q >> 1) * 16;
    uint32_t bRow[2], bXor[2];
    #pragma unroll
    for (int p = 0; p < 2; ++p) {
        int row = wn*32 + (2*p + (q >> 1))*8 + r;
        bRow[p] = (uint32_t)row * 128;
        bXor[p] = (uint32_t)(row & 7) * 16;
    }
    uint32_t bCsel = (uint32_t)(q & 1) * 16;

    float acc[MT][4][4];
    #pragma unroll
    for (int i = 0; i < MT; ++i)
        #pragma unroll
        for (int j = 0; j < 4; ++j)
            #pragma unroll
            for (int v = 0; v < 4; ++v) acc[i][j][v] = 0.f;

    int nk = K3 >> 6;

    auto load_tile = [&](int j, int stg) {
        int kt = j << 6;
        uint32_t sA = sbase + (uint32_t)stg*STAGE;
        uint32_t sB = sA + ABYTES;
        #pragma unroll
        for (int i = 0; i < (BM*8)/THREADS; ++i) {
            int c = tid + i*THREADS;
            int row = c >> 3, col16 = c & 7;
            uint32_t off = (uint32_t)(row*128 + col16*16);
            cpa16(sA + SWZ(off), A3 + (size_t)(m0+row)*K3 + kt + col16*8);
        }
        #pragma unroll
        for (int i = 0; i < (BN*8)/THREADS; ++i) {
            int c = tid + i*THREADS;
            int row = c >> 3, col16 = c & 7;
            uint32_t off = (uint32_t)(row*128 + col16*16);
            cpa16(sB + SWZ(off), B3 + (size_t)(n0+row)*K3 + kt + col16*8);
        }
        asm volatile("cp.async.commit_group;" ::: "memory");
    };

    load_tile(0, 0);
    if (nk > 1) load_tile(1, 1);

    for (int ki = 0; ki < nk; ++ki) {
        int stg = ki % 3;
        if (ki + 2 < nk) {
            load_tile(ki + 2, (ki + 2) % 3);
            asm volatile("cp.async.wait_group 2;" ::: "memory");
        } else if (ki + 1 < nk) {
            asm volatile("cp.async.wait_group 1;" ::: "memory");
        } else {
            asm volatile("cp.async.wait_group 0;" ::: "memory");
        }
        __syncthreads();

        uint32_t sA = sbase + (uint32_t)stg*STAGE;
        uint32_t sB = sA + ABYTES;
        #pragma unroll
        for (int kk = 0; kk < 4; ++kk) {
            uint32_t afr[MT][4];
            #pragma unroll
            for (int mt = 0; mt < MT; ++mt)
                ldm4(afr[mt], sA + aRow[mt] + (((uint32_t)(kk*32) + aCsel) ^ aXor[mt]));
            uint32_t bfr[2][4];
            #pragma unroll
            for (int p = 0; p < 2; ++p)
                ldm4(bfr[p], sB + bRow[p] + (((uint32_t)(kk*32) + bCsel) ^ bXor[p]));
            #pragma unroll
            for (int mt = 0; mt < MT; ++mt)
                #pragma unroll
                for (int nt = 0; nt < 4; ++nt)
                    mma16816(acc[mt][nt], afr[mt], bfr[nt >> 1][(nt & 1)*2], bfr[nt >> 1][(nt & 1)*2 + 1]);
        }
        __syncthreads();
    }

    float mult = alpha;
    if (amode == 1) { float t = g_tr[tridx]; mult = alpha / (t * t); }
    else if (amode == 2) mult *= g_kscale;

    int cr = lane >> 2, cc = (lane & 3) * 2;
    #pragma unroll
    for (int mt = 0; mt < MT; ++mt) {
        #pragma unroll
        for (int nt = 0; nt < 4; ++nt) {
            int gm = m0 + wm*(MT*16) + mt*16 + cr;
            int gn = n0 + wn*32 + nt*8 + cc;
            float2 v0, v1;
            v0.x = mult*acc[mt][nt][0]; v0.y = mult*acc[mt][nt][1];
            v1.x = mult*acc[mt][nt][2]; v1.y = mult*acc[mt][nt][3];
            if (beta != 0.f) {
                float2 d0 = *(const float2*)&Dm[(size_t)gm*ldd + gn];
                float2 d1 = *(const float2*)&Dm[(size_t)(gm+8)*ldd + gn];
                v0.x += beta*d0.x; v0.y += beta*d0.y;
                v1.x += beta*d1.x; v1.y += beta*d1.y;
            }
            *(float2*)&C[(size_t)gm*ldc + gn] = v0;
            *(float2*)&C[(size_t)(gm+8)*ldc + gn] = v1;
        }
    }
}

// ---------------- even/odd A^2 scan via mma.sync fp16 ----------------
// grid = 147 CTAs, 512 threads = 16 warps. Warp w owns cols [w*32, w*32+32).
// State: 32 rows (0-15 even chain y=x_{2s}, 16-31 odd chain z=x_{2s+1}),
// hi+lo fp16 in double-buffered smem. One A^2 stream covers 2 time-steps.
#define XP 1040u                  /* bytes per x row (512*2 + 16 pad) */
#define SEC (32u*XP)              /* one precision section (32 rows): 33280 B */
#define EOBUF (2u*SEC)            /* hi + lo: 66560 B */
#define EO_SMEM (2u*EOBUF)        /* double buffer: 133120 B */

__global__ void __launch_bounds__(512)
scan_eo_kernel(const float* __restrict__ Cc, const __half* __restrict__ Apk,
               const float* __restrict__ state0, const float* __restrict__ x1,
               float* __restrict__ states)
{
    extern __shared__ char sm[];
    uint32_t sbase = (uint32_t)__cvta_generic_to_shared(sm);
    int tid = threadIdx.x, wid = tid >> 5, lane = tid & 31;
    int gid = lane >> 2, tig = lane & 3;
    int q = lane >> 3, rr = lane & 7;
    uint32_t lrowE = (uint32_t)((q & 1)*8 + rr) * XP;
    uint32_t lrowO = lrowE + 16u*XP;
    uint32_t lcs  = (uint32_t)(q >> 1) * 16;

    int s0 = blockIdx.x * MCTS;
    int send = s0 + MCTS; if (send > 2048) send = 2048;
    int sstart = s0 - MCW; if (sstart < 0) sstart = 0;
    bool fromstate = (sstart == 0);

    // init buffer 0: rows 0-15 = even chain (state0 / 0), rows 16-31 = odd (x1 / 0)
    for (int i = tid; i < 32*512; i += 512) {
        int m = i >> 9, n = i & 511;
        float v = 0.f;
        if (fromstate) v = (m < 16) ? state0[m*DX + n] : x1[(m-16)*DX + n];
        __half h = __float2half(v);
        __half l = __float2half(v - __half2float(h));
        *(__half*)(sm + m*XP + n*2) = h;
        *(__half*)(sm + SEC + m*XP + n*2) = l;
    }
    __syncthreads();

    int nbase = wid * 32;
    int buf = 0;

    for (int s = sstart; s < send; ++s) {
        // accumulators init from c: even uses c_{2s}, odd uses c_{2s+1}
        float aE[4][4], aO[4][4];
        {
            const float* ce0 = Cc + ((size_t)gid*SEQL + 2*s)*DX;
            const float* ce1 = Cc + ((size_t)(gid+8)*SEQL + 2*s)*DX;
            #pragma unroll
            for (int nt = 0; nt < 4; ++nt) {
                int n = nbase + nt*8 + tig*2;
                float2 e0 = *(const float2*)(ce0 + n);
                float2 e1 = *(const float2*)(ce1 + n);
                float2 o0 = *(const float2*)(ce0 + DX + n);
                float2 o1 = *(const float2*)(ce1 + DX + n);
                aE[nt][0] = e0.x; aE[nt][1] = e0.y; aE[nt][2] = e1.x; aE[nt][3] = e1.y;
                aO[nt][0] = o0.x; aO[nt][1] = o0.y; aO[nt][2] = o1.x; aO[nt][3] = o1.y;
            }
        }
        uint32_t bh = sbase + (uint32_t)buf*EOBUF;
        uint32_t bl = bh + SEC;

        #pragma unroll 2
        for (int ktp = 0; ktp < 16; ++ktp) {
            uint32_t cb = (uint32_t)(ktp*64);
            uint32_t eh0[4], eh1[4], el0[4], el1[4];
            uint32_t oh0[4], oh1[4], ol0[4], ol1[4];
            ldm4(eh0, bh + lrowE + cb + lcs);
            ldm4(eh1, bh + lrowE + cb + 32 + lcs);
            ldm4(el0, bl + lrowE + cb + lcs);
            ldm4(el1, bl + lrowE + cb + 32 + lcs);
            ldm4(oh0, bh + lrowO + cb + lcs);
            ldm4(oh1, bh + lrowO + cb + 32 + lcs);
            ldm4(ol0, bl + lrowO + cb + lcs);
            ldm4(ol1, bl + lrowO + cb + 32 + lcs);
            #pragma unroll
            for (int nt = 0; nt < 4; ++nt) {
                uint4 bv = *(const uint4*)(Apk +
                    ((((size_t)(wid*4 + nt)*16 + ktp)*32 + lane) << 3));
                mmaf16(aE[nt], eh0, bv.x, bv.y);
                mmaf16(aE[nt], eh1, bv.z, bv.w);
                mmaf16(aE[nt], el0, bv.x, bv.y);
                mmaf16(aE[nt], el1, bv.z, bv.w);
                mmaf16(aO[nt], oh0, bv.x, bv.y);
                mmaf16(aO[nt], oh1, bv.z, bv.w);
                mmaf16(aO[nt], ol0, bv.x, bv.y);
                mmaf16(aO[nt], ol1, bv.z, bv.w);
            }
        }

        // epilogue: write next state to other buffer; states if in real range
        char* nb = sm + (buf ^ 1)*EOBUF;
        bool wr  = (s >= s0);
        bool wrO = wr && (s <= 2046);
        #pragma unroll
        for (int nt = 0; nt < 4; ++nt) {
            int n = nbase + nt*8 + tig*2;
            #pragma unroll
            for (int half = 0; half < 2; ++half) {
                int b = gid + half*8;
                float vE0 = aE[nt][half*2], vE1 = aE[nt][half*2+1];
                float vO0 = aO[nt][half*2], vO1 = aO[nt][half*2+1];
                __half hE0 = __float2half(vE0), hE1 = __float2half(vE1);
                __half hO0 = __float2half(vO0), hO1 = __float2half(vO1);
                __half lE0 = __float2half(vE0 - __half2float(hE0));
                __half lE1 = __float2half(vE1 - __half2float(hE1));
                __half lO0 = __float2half(vO0 - __half2float(hO0));
                __half lO1 = __float2half(vO1 - __half2float(hO1));
                *(__half2*)(nb + b*XP + n*2)              = __halves2half2(hE0, hE1);
                *(__half2*)(nb + (16+b)*XP + n*2)         = __halves2half2(hO0, hO1);
                *(__half2*)(nb + SEC + b*XP + n*2)        = __halves2half2(lE0, lE1);
                *(__half2*)(nb + SEC + (16+b)*XP + n*2)   = __halves2half2(lO0, lO1);
                if (wr)
                    *(float2*)(states + ((size_t)b*(SEQL+1) + 2*s + 2)*DX + n) = make_float2(vE0, vE1);
                if (wrO)
                    *(float2*)(states + ((size_t)b*(SEQL+1) + 2*s + 3)*DX + n) = make_float2(vO0, vO1);
            }
        }
        __syncthreads();
        buf ^= 1;
    }
}

// ---------------- host ----------------
static void* symaddr(const void* sym) {
    void* p = nullptr;
    cudaGetSymbolAddress(&p, sym);
    return p;
}

static void SPLIT(const float* src, __nv_bfloat16* dst, long long rs, long long cs,
                  int K, long long rows, int bmode, int rpb = 0, long long bstr = 0)
{
    long long total = rows * (long long)K;
    int grid = (int)((total + 255) / 256);
    split3_kernel<<<grid, 256>>>(src, dst, rs, cs, K, total, rpb, bstr, bmode);
}

static void SPLITD(const float* src, __nv_bfloat16* dstA, __nv_bfloat16* dstB,
                   long long rs, long long cs, int K, long long rows, int tr_slot)
{
    long long total = rows * (long long)K;
    int grid = (int)((total + 255) / 256);
    split3_dual_kernel<<<grid, 256>>>(src, dstA, dstB, rs, cs, K, total, tr_slot);
}

static void TCG(const __nv_bfloat16* A3, const __nv_bfloat16* B3, const float* Dm, float* Cp,
                int M, int N, int K3, int ldd, int ldc, int amode, float alpha, float beta,
                int tridx = 0)
{
    if (M >= 1024) {
        dim3 g(N/128, M/128);
        tc_gemm<4,4><<<g, 256, 98304>>>(A3, B3, Dm, Cp, K3, ldd, ldc, amode, alpha, beta, tridx);
    } else {
        dim3 g(N/64, M/64);
        tc_gemm<2,2><<<g, 128, 49152>>>(A3, B3, Dm, Cp, K3, ldd, ldc, amode, alpha, beta, tridx);
    }
}

extern "C" void kernel_launch(void* const* d_in, const int* in_sizes, int n_in,
                              void* d_out, int out_size)
{
    const float *u = nullptr, *state = nullptr, *S = nullptr, *Kraw = nullptr;
    for (int i = 0; i < n_in; ++i) {
        long long sz = in_sizes[i];
        if      (sz == (long long)NB*SEQL*DU) u     = (const float*)d_in[i];
        else if (sz == (long long)NB*DX)      state = (const float*)d_in[i];
        else if (sz == (long long)DX*DX)      S     = (const float*)d_in[i];
        else if (sz == (long long)DK*DK)      Kraw  = (const float*)d_in[i];
    }
    float* out = (float*)d_out;

    cudaFuncSetAttribute((const void*)tc_gemm<4,4>, cudaFuncAttributeMaxDynamicSharedMemorySize, 98304);
    cudaFuncSetAttribute((const void*)tc_gemm<2,2>, cudaFuncAttributeMaxDynamicSharedMemorySize, 49152);
    cudaFuncSetAttribute((const void*)scan_eo_kernel, cudaFuncAttributeMaxDynamicSharedMemorySize, EO_SMEM);

    float* pM0    = (float*)symaddr(g_M0);
    float* pM1    = (float*)symaddr(g_M1);
    float* pXa    = (float*)symaddr(g_Xa);
    float* pXb    = (float*)symaddr(g_Xb);
    float* pP     = (float*)symaddr(g_P);
    float* pT1    = (float*)symaddr(g_T1);
    float* pAmat  = (float*)symaddr(g_Amat);
    float* pBm    = (float*)symaddr(g_Bm);
    float* pE     = (float*)symaddr(g_E);
    float* pBu    = (float*)symaddr(g_Bu);
    float* pX1    = (float*)symaddr(g_X1);
    float* pFall  = (float*)symaddr(g_states_fallback);
    __half* pApk  = (__half*)symaddr(g_Apk);

    __nv_bfloat16* pcBig1 = (__nv_bfloat16*)symaddr(c_big1);
    __nv_bfloat16* pcBig2 = (__nv_bfloat16*)symaddr(c_big2);
    __nv_bfloat16* pcKT   = (__nv_bfloat16*)symaddr(c_kt);
    __nv_bfloat16* pcM    = (__nv_bfloat16*)symaddr(c_m);
    __nv_bfloat16* pcS    = (__nv_bfloat16*)symaddr(c_s);
    __nv_bfloat16* pcST   = (__nv_bfloat16*)symaddr(c_st);
    __nv_bfloat16* pcW1   = (__nv_bfloat16*)symaddr(c_w1);
    __nv_bfloat16* pcW2   = (__nv_bfloat16*)symaddr(c_w2);
    __nv_bfloat16* pcW3   = (__nv_bfloat16*)symaddr(c_w3);
    __nv_bfloat16* pcW4   = (__nv_bfloat16*)symaddr(c_w4);
    __nv_bfloat16* pcDw   = (__nv_bfloat16*)symaddr(c_dw);

    float* states = ((long long)out_size >= (long long)OUT_ELEMS + (long long)ST_ELEMS)
                    ? (out + OUT_ELEMS) : pFall;

    // --- init (g_tr=0, X0=I) ---
    init_kernel<<<(DX*DX + 255)/256, 256>>>();

    // --- sigma: M0 = K^T K, 8 trace-normalized squarings (trace fused into split),
    //     Frobenius finish (estimator exponent 512). ---
    SPLITD(Kraw, pcKT, pcM, 1, DK, DK, DK, -1);             // K^T, both sides
    TCG(pcKT, pcM, nullptr, pM0, DK, DK, 3*DK, 0, DK, 0, 1.f, 0.f);
    float* Ms[2] = {pM0, pM1};
    for (int i = 0; i < 8; ++i) {
        SPLITD(Ms[i & 1], pcKT, pcM, DK, 1, DK, DK, i);     // split + tr(M_i) -> g_tr[i]
        TCG(pcKT, pcM, nullptr, Ms[(i+1) & 1], DK, DK, 3*DK, 0, DK, 1, 1.f, 0.f, i);
    }
    frob_part<<<64,256>>>(Ms[0]);                           // M_8 in buffer 0
    finalize_kernel<<<1,1>>>();

    // --- Sinv via Newton-Schulz: X <- 2X - X S X, 4 iters ---
    SPLIT(S, pcS, DX, 1, DX, DX, 0);                        // S rows, A-side (once)
    float* Xc = pXa; float* Xn = pXb;
    for (int it = 0; it < 4; ++it) {
        SPLIT(Xc, pcW1, DX, 1, DX, DX, 0);                  // Xc rows, A-side
        SPLIT(Xc, pcW2, 1, DX, DX, DX, 1);                  // Xc^T, B-side
        TCG(pcS, pcW2, nullptr, pP, DX, DX, 1536, 0, DX, 0, 1.f, 0.f);   // P = S@Xc
        SPLIT(pP, pcW3, 1, DX, DX, DX, 1);                  // P^T, B-side
        TCG(pcW1, pcW3, Xc, Xn, DX, DX, 1536, DX, DX, 0, -1.f, 2.f);     // Xn = 2Xc - Xc@P
        float* tmp = Xc; Xc = Xn; Xn = tmp;
    }
    // Xc == pXa == Sinv

    // --- assemble A, B, C, D (all carry kscale; GAMMA=1) ---
    SPLIT(Xc, pcW4, DX, 1, DX, DX, 0);                      // Sinv rows, A-side
    SPLIT(S, pcST, 1, DX, DX, DX, 1);                       // S^T, B-side
    SPLIT(Kraw, pcW1, DK, 1, DX, DX, 0);                    // K11 rows, A-side [512 x 512]
    TCG(pcW1, pcST, nullptr, pT1, DX, DX, 1536, 0, DX, 2, 1.f, 0.f);     // T1 = ks*K11@S
    SPLIT(pT1, pcW2, 1, DX, DX, DX, 1);                     // T1^T, B-side
    TCG(pcW4, pcW2, nullptr, pAmat, DX, DX, 1536, 0, DX, 0, 1.f, 0.f);   // A = Sinv@T1
    SPLIT(Kraw + DX, pcW3, 1, DK, DX, DU, 1);               // K12^T, B-side [256 x 512]
    TCG(pcW4, pcW3, nullptr, pBm, DX, DU, 1536, 0, DU, 2, 1.f, 0.f);     // B = ks*Sinv@K12
    SPLIT(Kraw + (size_t)DX*DK, pcW1, DK, 1, DX, DOUT, 0);  // K21 rows, A-side [256 x 512]
    TCG(pcW1, pcST, nullptr, pE, DOUT, DX, 1536, 0, DK, 2, 1.f, 0.f);    // C = ks*K21@S
    dcopy_kernel<<<(DOUT*DU)/256, 256>>>(Kraw);             // D block of E

    // --- A^2 and G = A@B for the even/odd scan ---
    SPLIT(pAmat, pcW2, DX, 1, DX, DX, 0);                   // A rows, A-side
    SPLIT(pAmat, pcW3, 1, DX, DX, DX, 1);                   // A^T, B-side
    TCG(pcW2, pcW3, nullptr, pT1, DX, DX, 1536, 0, DX, 0, 1.f, 0.f);     // A2 = A@A (fp32)
    pack_frag_kernel<<<(DX*DX)/256, 256>>>(pT1);            // A2 -> fp16 fragments
    SPLIT(pBm, pcW4, 1, DU, DX, DU, 1);                     // Bm^T, B-side [256 x 512]
    TCG(pcW2, pcW4, nullptr, pP, DX, DU, 1536, 0, DU, 0, 1.f, 0.f);      // G = A@Bm [512x256]
    gb_kernel<<<(DX*DX)/256, 256>>>(pP);                    // GBf = [G | Bm] -> g_Xb
    SPLIT(pXb, pcW1, DX, 1, DX, DX, 1);                     // GB B-side [512 x 1536]

    // --- c = u2 @ GB^T  (c_t = G u_t + B u_{t+1}), [65536 x 512] ---
    split3_u2_kernel<<<(NB*SEQL*DX)/256, 256>>>(u, pcBig1); // u2 A-side [65536 x 1536]
    TCG(pcBig1, pcW1, nullptr, pBu, NB*SEQL, DX, 1536, 0, DX, 0, 1.f, 0.f);

    // --- states[0], states[1]=x1, then even/odd scan ---
    state0_kernel<<<(NB*DX)/256, 256>>>(state, states);
    x1_kernel<<<NB, 512>>>(state, u, states);
    scan_eo_kernel<<<EO_NCH, 512, EO_SMEM>>>(pBu, pApk, state, pX1, states);

    // --- output = pre_states @ C^T + u @ D^T ---
    SPLIT(pE, pcW2, DK, 1, DX, DOUT, 1);                    // Cw rows, B-side [256 x 512]
    SPLIT(pE + DX, pcDw, DK, 1, DU, DOUT, 1);               // Dw rows, B-side [256 x 256]
    SPLIT(u, pcBig2, DU, 1, DU, (long long)NB*SEQL, 0);     // u3, A-side [65536 x 768]
    SPLIT(states, pcBig1, DX, 1, DX, (long long)NB*SEQL, 0, SEQL, (long long)(SEQL+1)*DX);
    TCG(pcBig1, pcW2, nullptr, out, NB*SEQL, DOUT, 1536, 0, DOUT, 0, 1.f, 0.f);
    TCG(pcBig2, pcDw, out, out, NB*SEQL, DOUT, 768, DOUT, DOUT, 0, 1.f, 1.f);
}

// round 15
// speedup vs baseline: 1.6499x; 1.1267x over previous
#include <cuda_runtime.h>
#include <cuda_bf16.h>
#include <cuda_fp16.h>
#include <math.h>
#include <stdint.h>

#define DX 512
#define DU 256
#define DOUT 256
#define DK 768
#define NB 16
#define SEQL 4096
#define MCTS 14         // macro steps per chunk (147*14 = 2058 >= 2048)
#define MCW 28          // macro warmup (56 time-steps)
#define EO_NCH 147
#define OUT_ELEMS (NB*SEQL*DOUT)           /* 16777216 */
#define ST_ELEMS  ((size_t)NB*(SEQL+1)*DX) /* 33562624 */

// ---------------- device scratch (static; no runtime allocation) ----------------
__device__ float g_Xa[DX*DX];        // X (NS iterate) fp32
__device__ float g_Xb[DX*DX];
__device__ float g_Amat[DX*DX];
__device__ float g_A2[DX*DX];
__device__ float g_G[DX*DU];
__device__ __half g_Apk[DX*DX];      // A^2 in mma B-fragment layout, fp16
__device__ float g_Bm[DX*DU];
__device__ float g_Bu[(size_t)NB*SEQL*DX];   // c_t = G u_t + B u_{t+1}
__device__ float g_X1[NB*DX];
__device__ float g_states_fallback[(size_t)NB*(SEQL+1)*DX];
__device__ float g_tr[10];           // 0..7 traces, 8 frobenius
__device__ float g_kscale;

// bf16 split buffers. A-side layout [h,l,h]; B-side layout [h,h,l].
__device__ __nv_bfloat16 c_kt [DK*2304];   // M even, A-side
__device__ __nv_bfloat16 c_m  [DK*2304];   // M even, B-side
__device__ __nv_bfloat16 c_kt2[DK*2304];   // M odd, A-side
__device__ __nv_bfloat16 c_m2 [DK*2304];   // M odd, B-side
__device__ __nv_bfloat16 c_s  [DX*1536];   // S rows, A-side
__device__ __nv_bfloat16 c_st [DX*1536];   // S^T, B-side
__device__ __nv_bfloat16 c_xr0[DX*1536];   // X rows A-side ping
__device__ __nv_bfloat16 c_xr1[DX*1536];   // pong
__device__ __nv_bfloat16 c_xt0[DX*1536];   // X^T B-side ping
__device__ __nv_bfloat16 c_xt1[DX*1536];   // pong
__device__ __nv_bfloat16 c_pt [DX*1536];   // P^T B-side
__device__ __nv_bfloat16 c_k11[DX*1536];   // K11 rows A-side
__device__ __nv_bfloat16 c_k12[DOUT*1536]; // K12^T B-side
__device__ __nv_bfloat16 c_k21[DOUT*1536]; // K21 rows A-side
__device__ __nv_bfloat16 c_t1t[DX*1536];   // T1^T B-side
__device__ __nv_bfloat16 c_ar [DX*1536];   // A rows A-side
__device__ __nv_bfloat16 c_at [DX*1536];   // A^T B-side
__device__ __nv_bfloat16 c_bmt[DOUT*1536]; // Bm^T B-side
__device__ __nv_bfloat16 c_gb [DX*1536];   // [G|Bm] B-side rows
__device__ __nv_bfloat16 c_cw [DOUT*1536]; // Cw rows B-side
__device__ __nv_bfloat16 c_dw [DOUT*768];  // Dw rows B-side
__device__ __nv_bfloat16 c_big1[(size_t)65536*1536]; // u2 pre-scan / states3 post-scan (A-side)
__device__ __nv_bfloat16 c_big2[(size_t)65536*768];  // u3 A-side

// ---------------- split write helpers ----------------
__device__ __forceinline__ void wA1(__nv_bfloat16* d, int K, int k, float x) {
    __nv_bfloat16 h = __float2bfloat16(x);
    __nv_bfloat16 l = __float2bfloat16(x - __bfloat162float(h));
    d[k] = h; d[K+k] = l; d[2*K+k] = h;
}
__device__ __forceinline__ void wB1(__nv_bfloat16* d, int K, int k, float x) {
    __nv_bfloat16 h = __float2bfloat16(x);
    __nv_bfloat16 l = __float2bfloat16(x - __bfloat162float(h));
    d[k] = h; d[K+k] = h; d[2*K+k] = l;
}

// ---------------- prep: all input-derived splits + init, one kernel ----------------
// Ranges: [0,262144) S/X1/K11; [262144,393216) K12^T; [393216,524288) K21;
//         [524288,1114112) K^T dual.
__global__ void prep_kernel(const float* __restrict__ S, const float* __restrict__ Kraw) {
    int idx = blockIdx.x * blockDim.x + threadIdx.x;
    if (idx < 10) g_tr[idx] = 0.f;
    if (idx < 262144) {
        int i = idx >> 9, j = idx & 511;
        float sv = S[idx];
        wA1(c_s  + (size_t)i*1536, DX, j, sv);
        wB1(c_st + (size_t)j*1536, DX, i, sv);
        float xv = ((i == j) ? 2.f : 0.f) - sv;
        g_Xa[idx] = xv;
        wA1(c_xr0 + (size_t)i*1536, DX, j, xv);
        wB1(c_xt0 + (size_t)j*1536, DX, i, xv);
        float kv = Kraw[(size_t)i*DK + j];
        wA1(c_k11 + (size_t)i*1536, DX, j, kv);
    } else if (idx < 393216) {
        int t = idx - 262144, n = t >> 9, k = t & 511;
        float v = Kraw[(size_t)k*DK + DX + n];      // K12^T[n][k] = K[k][512+n]
        wB1(c_k12 + (size_t)n*1536, DX, k, v);
    } else if (idx < 524288) {
        int t = idx - 393216, o = t >> 9, k = t & 511;
        float v = Kraw[(size_t)(DX+o)*DK + k];      // K21[o][k]
        wA1(c_k21 + (size_t)o*1536, DX, k, v);
    } else if (idx < 1114112) {
        int t = idx - 524288, i = t / DK, j = t - i*DK;
        float v = Kraw[(size_t)j*DK + i];           // K^T[i][j]
        wA1(c_kt + (size_t)i*2304, DK, j, v);
        wB1(c_m  + (size_t)i*2304, DK, j, v);
    }
}

// L = sum_{i=0..7} 2^-i log(tr_i) + 2^-9 log(g_tr[8]);  sigma = exp(L/2)
__global__ void finalize_kernel() {
    if (threadIdx.x != 0) return;
    double L = 0.0, w = 1.0;
    for (int i = 0; i < 8; ++i) { L += w * log((double)g_tr[i]); w *= 0.5; }
    L += (w * 0.5) * log((double)g_tr[8]);
    float sigma = (float)exp(0.5 * L);
    if (sigma < 1e-5f) sigma = 1e-5f;
    g_kscale = 1.f / (sigma + 0.002f);
}

// pack src (fp32, 512x512) -> fp16 fragments for mma m16n8k16 B operand.
__global__ void pack_frag_kernel(const float* __restrict__ src) {
    int idx = blockIdx.x * blockDim.x + threadIdx.x;
    int i = idx & 7, lane = (idx >> 3) & 31, ktp = (idx >> 8) & 15, nt = idx >> 12;
    int t = i >> 2, j = i & 3;
    int tig = lane & 3, gid = lane >> 2;
    int k = tig*2 + (j & 1) + ((j >> 1) * 8);
    int h = (2*ktp + t)*16 + k;
    int n = nt*8 + gid;
    g_Apk[idx] = __float2half(src[(size_t)n*DX + h]);
}

// Dw rows B-side: Dw[o][h] = ks*K22[o][h]
__global__ void dw_kernel(const float* __restrict__ Kraw) {
    int idx = blockIdx.x * blockDim.x + threadIdx.x;   // 256*256
    int o = idx >> 8, h = idx & 255;
    float v = g_kscale * Kraw[(size_t)(DX+o)*DK + DX + h];
    wB1(c_dw + (size_t)o*768, DU, h, v);
}

// GB B-side rows from fp32 G and Bm
__global__ void gb_kernel() {
    int idx = blockIdx.x * blockDim.x + threadIdx.x;   // 512*512
    int o = idx >> 9, k = idx & 511;
    float v = (k < DU) ? g_G[o*DU + k] : g_Bm[(size_t)o*DU + (k - DU)];
    wB1(c_gb + (size_t)o*1536, DX, k, v);
}

// u2 A-side [65536 x 1536] + u3 A-side [65536 x 768], one pass over u
__global__ void u23_kernel(const float* __restrict__ u) {
    long long idx = (long long)blockIdx.x * 256 + threadIdx.x;   // 65536*512
    long long r = idx >> 9;
    int k = (int)(idx & 511);
    int b = (int)(r >> 12), t = (int)(r & 4095);
    float x;
    if (k < DU) {
        x = u[((size_t)b*SEQL + t)*DU + k];
        wA1(c_big2 + r*768, DU, k, x);
    } else {
        x = (t + 1 < SEQL) ? u[((size_t)b*SEQL + t + 1)*DU + (k - DU)] : 0.f;
    }
    wA1(c_big1 + r*1536, DX, k, x);
}

__global__ void state0_kernel(const float* __restrict__ st, float* __restrict__ states) {
    int idx = blockIdx.x * blockDim.x + threadIdx.x;   // NB*DX
    int b = idx >> 9, n = idx & 511;
    float v = st[idx];
    states[(size_t)b*(SEQL+1)*DX + n] = v;
    wA1(c_big1 + ((size_t)b*SEQL)*1536, DX, n, v);     // states3 row t=0
}

// x1 = A @ state0 + Bm @ u_0 (exact fp32); writes states row 1 + states3 row 1
__global__ void x1_kernel(const float* __restrict__ state0, const float* __restrict__ u,
                          float* __restrict__ states) {
    __shared__ float s0[DX];
    __shared__ float u0[DU];
    int b = blockIdx.x, n = threadIdx.x;
    s0[n] = state0[b*DX + n];
    if (n < DU) u0[n] = u[(size_t)b*SEQL*DU + n];
    __syncthreads();
    float acc = 0.f;
    const float* arow = g_Amat + (size_t)n*DX;
    for (int h = 0; h < DX; ++h) acc += arow[h] * s0[h];
    const float* brow = g_Bm + (size_t)n*DU;
    for (int h = 0; h < DU; ++h) acc += brow[h] * u0[h];
    g_X1[b*DX + n] = acc;
    states[((size_t)b*(SEQL+1) + 1)*DX + n] = acc;
    wA1(c_big1 + ((size_t)b*SEQL + 1)*1536, DX, n, acc);
}

// ---------------- tensor-core bf16-split GEMM with fused split epilogue ----------------
__device__ __forceinline__ void cpa16(uint32_t s, const void* g) {
    asm volatile("cp.async.cg.shared.global [%0], [%1], 16;" :: "r"(s), "l"(g));
}
__device__ __forceinline__ void ldm4(uint32_t* f, uint32_t addr) {
    asm volatile("ldmatrix.sync.aligned.m8n8.x4.shared.b16 {%0,%1,%2,%3}, [%4];"
                 : "=r"(f[0]), "=r"(f[1]), "=r"(f[2]), "=r"(f[3]) : "r"(addr));
}
__device__ __forceinline__ void mma16816(float* c, const uint32_t* a, uint32_t b0, uint32_t b1) {
    asm volatile("mma.sync.aligned.m16n8k16.row.col.f32.bf16.bf16.f32 "
                 "{%0,%1,%2,%3}, {%4,%5,%6,%7}, {%8,%9}, {%0,%1,%2,%3};"
                 : "+f"(c[0]), "+f"(c[1]), "+f"(c[2]), "+f"(c[3])
                 : "r"(a[0]), "r"(a[1]), "r"(a[2]), "r"(a[3]), "r"(b0), "r"(b1));
}
__device__ __forceinline__ void mmaf16(float* c, const uint32_t* a, uint32_t b0, uint32_t b1) {
    asm volatile("mma.sync.aligned.m16n8k16.row.col.f32.f16.f16.f32 "
                 "{%0,%1,%2,%3}, {%4,%5,%6,%7}, {%8,%9}, {%0,%1,%2,%3};"
                 : "+f"(c[0]), "+f"(c[1]), "+f"(c[2]), "+f"(c[3])
                 : "r"(a[0]), "r"(a[1]), "r"(a[2]), "r"(a[3]), "r"(b0), "r"(b1));
}
#define SWZ(x) ((x) ^ (((x) >> 3) & 0x70))

__device__ __forceinline__ void wpairA(__nv_bfloat16* d, int r, int c, int N, float v0, float v1) {
    __nv_bfloat16 h0 = __float2bfloat16(v0), h1 = __float2bfloat16(v1);
    __nv_bfloat16 l0 = __float2bfloat16(v0 - __bfloat162float(h0));
    __nv_bfloat16 l1 = __float2bfloat16(v1 - __bfloat162float(h1));
    size_t base = (size_t)r*3*N + c;
    __nv_bfloat162 hh; hh.x = h0; hh.y = h1;
    __nv_bfloat162 ll; ll.x = l0; ll.y = l1;
    *(__nv_bfloat162*)(d + base) = hh;
    *(__nv_bfloat162*)(d + base + N) = ll;
    *(__nv_bfloat162*)(d + base + 2*N) = hh;
}
__device__ __forceinline__ void wpairBr(__nv_bfloat16* d, int r, int c, int N, float v0, float v1) {
    __nv_bfloat16 h0 = __float2bfloat16(v0), h1 = __float2bfloat16(v1);
    __nv_bfloat16 l0 = __float2bfloat16(v0 - __bfloat162float(h0));
    __nv_bfloat16 l1 = __float2bfloat16(v1 - __bfloat162float(h1));
    size_t base = (size_t)r*3*N + c;
    __nv_bfloat162 hh; hh.x = h0; hh.y = h1;
    __nv_bfloat162 ll; ll.x = l0; ll.y = l1;
    *(__nv_bfloat162*)(d + base) = hh;
    *(__nv_bfloat162*)(d + base + N) = hh;
    *(__nv_bfloat162*)(d + base + 2*N) = ll;
}
__device__ __forceinline__ void wpairBt(__nv_bfloat16* d, int r, int c, int M, float v0, float v1) {
    // transposed: element (r,c) of C -> row c of d (length 3M), position r
    __nv_bfloat16 h0 = __float2bfloat16(v0), h1 = __float2bfloat16(v1);
    __nv_bfloat16 l0 = __float2bfloat16(v0 - __bfloat162float(h0));
    __nv_bfloat16 l1 = __float2bfloat16(v1 - __bfloat162float(h1));
    size_t b0 = (size_t)c*3*M + r, b1 = (size_t)(c+1)*3*M + r;
    d[b0] = h0; d[b0+M] = h0; d[b0+2*M] = l0;
    d[b1] = h1; d[b1+M] = h1; d[b1+2*M] = l1;
}

template<int MT, int WN>
__global__ __launch_bounds__(WN*64)
void tc_gemm(const __nv_bfloat16* __restrict__ A3, const __nv_bfloat16* __restrict__ B3,
             const float* __restrict__ Dm, float* __restrict__ Cp,
             __nv_bfloat16* outA, __nv_bfloat16* outBr, __nv_bfloat16* outBt,
             int K3, int N, int M, int ldd, int ldc,
             int amode, float alpha, float beta, int tridx, int trslot, int frobslot)
{
    constexpr int BM = MT*32;
    constexpr int BN = WN*32;
    constexpr int THREADS = WN*64;
    constexpr uint32_t ABYTES = BM*128;
    constexpr uint32_t BBYTES = BN*128;
    constexpr uint32_t STAGE = ABYTES + BBYTES;

    extern __shared__ char smem[];
    uint32_t sbase = (uint32_t)__cvta_generic_to_shared(smem);

    int tid = threadIdx.x;
    int wid = tid >> 5, lane = tid & 31;
    int wm = wid & 1, wn = wid >> 1;
    int m0 = blockIdx.y * BM, n0 = blockIdx.x * BN;

    int q = lane >> 3, r = lane & 7;
    uint32_t aRow[MT], aXor[MT];
    #pragma unroll
    for (int mt = 0; mt < MT; ++mt) {
        int row = wm*(MT*16) + mt*16 + (q & 1)*8 + r;
        aRow[mt] = (uint32_t)row * 128;
        aXor[mt] = (uint32_t)(row & 7) * 16;
    }
    uint32_t aCsel = (uint32_t)(q >> 1) * 16;
    uint32_t bRow[2], bXor[2];
    #pragma unroll
    for (int p = 0; p < 2; ++p) {
        int row = wn*32 + (2*p + (q >> 1))*8 + r;
        bRow[p] = (uint32_t)row * 128;
        bXor[p] = (uint32_t)(row & 7) * 16;
    }
    uint32_t bCsel = (uint32_t)(q & 1) * 16;

    float acc[MT][4][4];
    #pragma unroll
    for (int i = 0; i < MT; ++i)
        #pragma unroll
        for (int j = 0; j < 4; ++j)
            #pragma unroll
            for (int v = 0; v < 4; ++v) acc[i][j][v] = 0.f;

    int nk = K3 >> 6;

    auto load_tile = [&](int j, int stg) {
        int kt = j << 6;
        uint32_t sA = sbase + (uint32_t)stg*STAGE;
        uint32_t sB = sA + ABYTES;
        #pragma unroll
        for (int i = 0; i < (BM*8)/THREADS; ++i) {
            int c = tid + i*THREADS;
            int row = c >> 3, col16 = c & 7;
            uint32_t off = (uint32_t)(row*128 + col16*16);
            cpa16(sA + SWZ(off), A3 + (size_t)(m0+row)*K3 + kt + col16*8);
        }
        #pragma unroll
        for (int i = 0; i < (BN*8)/THREADS; ++i) {
            int c = tid + i*THREADS;
            int row = c >> 3, col16 = c & 7;
            uint32_t off = (uint32_t)(row*128 + col16*16);
            cpa16(sB + SWZ(off), B3 + (size_t)(n0+row)*K3 + kt + col16*8);
        }
        asm volatile("cp.async.commit_group;" ::: "memory");
    };

    load_tile(0, 0);
    if (nk > 1) load_tile(1, 1);

    for (int ki = 0; ki < nk; ++ki) {
        int stg = ki % 3;
        if (ki + 2 < nk) {
            load_tile(ki + 2, (ki + 2) % 3);
            asm volatile("cp.async.wait_group 2;" ::: "memory");
        } else if (ki + 1 < nk) {
            asm volatile("cp.async.wait_group 1;" ::: "memory");
        } else {
            asm volatile("cp.async.wait_group 0;" ::: "memory");
        }
        __syncthreads();

        uint32_t sA = sbase + (uint32_t)stg*STAGE;
        uint32_t sB = sA + ABYTES;
        #pragma unroll
        for (int kk = 0; kk < 4; ++kk) {
            uint32_t afr[MT][4];
            #pragma unroll
            for (int mt = 0; mt < MT; ++mt)
                ldm4(afr[mt], sA + aRow[mt] + (((uint32_t)(kk*32) + aCsel) ^ aXor[mt]));
            uint32_t bfr[2][4];
            #pragma unroll
            for (int p = 0; p < 2; ++p)
                ldm4(bfr[p], sB + bRow[p] + (((uint32_t)(kk*32) + bCsel) ^ bXor[p]));
            #pragma unroll
            for (int mt = 0; mt < MT; ++mt)
                #pragma unroll
                for (int nt = 0; nt < 4; ++nt)
                    mma16816(acc[mt][nt], afr[mt], bfr[nt >> 1][(nt & 1)*2], bfr[nt >> 1][(nt & 1)*2 + 1]);
        }
        __syncthreads();
    }

    float mult = alpha;
    if (amode == 1) { float t = g_tr[tridx]; mult = alpha / (t * t); }
    else if (amode == 2) mult *= g_kscale;

    float fsum = 0.f;
    int cr = lane >> 2, cc = (lane & 3) * 2;
    #pragma unroll
    for (int mt = 0; mt < MT; ++mt) {
        #pragma unroll
        for (int nt = 0; nt < 4; ++nt) {
            int gm = m0 + wm*(MT*16) + mt*16 + cr;
            int gn = n0 + wn*32 + nt*8 + cc;
            float v0 = mult*acc[mt][nt][0], v1 = mult*acc[mt][nt][1];
            float v2 = mult*acc[mt][nt][2], v3 = mult*acc[mt][nt][3];
            if (beta != 0.f) {
                float2 d0 = *(const float2*)&Dm[(size_t)gm*ldd + gn];
                float2 d1 = *(const float2*)&Dm[(size_t)(gm+8)*ldd + gn];
                v0 += beta*d0.x; v1 += beta*d0.y;
                v2 += beta*d1.x; v3 += beta*d1.y;
            }
            if (Cp) {
                *(float2*)&Cp[(size_t)gm*ldc + gn] = make_float2(v0, v1);
                *(float2*)&Cp[(size_t)(gm+8)*ldc + gn] = make_float2(v2, v3);
            }
            if (outA) {
                wpairA(outA, gm, gn, N, v0, v1);
                wpairA(outA, gm+8, gn, N, v2, v3);
            }
            if (outBr) {
                wpairBr(outBr, gm, gn, N, v0, v1);
                wpairBr(outBr, gm+8, gn, N, v2, v3);
            }
            if (outBt) {
                wpairBt(outBt, gm, gn, M, v0, v1);
                wpairBt(outBt, gm+8, gn, M, v2, v3);
            }
            if (trslot >= 0) {
                if (gm == gn)       atomicAdd(&g_tr[trslot], v0);
                if (gm == gn+1)     atomicAdd(&g_tr[trslot], v1);
                if (gm+8 == gn)     atomicAdd(&g_tr[trslot], v2);
                if (gm+8 == gn+1)   atomicAdd(&g_tr[trslot], v3);
            }
            if (frobslot >= 0) fsum += v0*v0 + v1*v1 + v2*v2 + v3*v3;
        }
    }
    if (frobslot >= 0) {
        #pragma unroll
        for (int o = 16; o > 0; o >>= 1)
            fsum += __shfl_xor_sync(0xFFFFFFFF, fsum, o);
        if (lane == 0) atomicAdd(&g_tr[frobslot], fsum);
    }
}

// ---------------- even/odd A^2 scan via mma.sync fp16 ----------------
#define XP 1040u
#define SEC (32u*XP)
#define EOBUF (2u*SEC)
#define EO_SMEM (2u*EOBUF)

__global__ void __launch_bounds__(512)
scan_eo_kernel(const float* __restrict__ Cc, const __half* __restrict__ Apk,
               const float* __restrict__ state0, const float* __restrict__ x1,
               float* __restrict__ states)
{
    extern __shared__ char sm[];
    uint32_t sbase = (uint32_t)__cvta_generic_to_shared(sm);
    int tid = threadIdx.x, wid = tid >> 5, lane = tid & 31;
    int gid = lane >> 2, tig = lane & 3;
    int q = lane >> 3, rr = lane & 7;
    uint32_t lrowE = (uint32_t)((q & 1)*8 + rr) * XP;
    uint32_t lrowO = lrowE + 16u*XP;
    uint32_t lcs  = (uint32_t)(q >> 1) * 16;

    int s0 = blockIdx.x * MCTS;
    int send = s0 + MCTS; if (send > 2048) send = 2048;
    int sstart = s0 - MCW; if (sstart < 0) sstart = 0;
    bool fromstate = (sstart == 0);

    for (int i = tid; i < 32*512; i += 512) {
        int m = i >> 9, n = i & 511;
        float v = 0.f;
        if (fromstate) v = (m < 16) ? state0[m*DX + n] : x1[(m-16)*DX + n];
        __half h = __float2half(v);
        __half l = __float2half(v - __half2float(h));
        *(__half*)(sm + m*XP + n*2) = h;
        *(__half*)(sm + SEC + m*XP + n*2) = l;
    }
    __syncthreads();

    int nbase = wid * 32;
    int buf = 0;

    for (int s = sstart; s < send; ++s) {
        float aE[4][4], aO[4][4];
        {
            const float* ce0 = Cc + ((size_t)gid*SEQL + 2*s)*DX;
            const float* ce1 = Cc + ((size_t)(gid+8)*SEQL + 2*s)*DX;
            #pragma unroll
            for (int nt = 0; nt < 4; ++nt) {
                int n = nbase + nt*8 + tig*2;
                float2 e0 = *(const float2*)(ce0 + n);
                float2 e1 = *(const float2*)(ce1 + n);
                float2 o0 = *(const float2*)(ce0 + DX + n);
                float2 o1 = *(const float2*)(ce1 + DX + n);
                aE[nt][0] = e0.x; aE[nt][1] = e0.y; aE[nt][2] = e1.x; aE[nt][3] = e1.y;
                aO[nt][0] = o0.x; aO[nt][1] = o0.y; aO[nt][2] = o1.x; aO[nt][3] = o1.y;
            }
        }
        uint32_t bh = sbase + (uint32_t)buf*EOBUF;
        uint32_t bl = bh + SEC;

        #pragma unroll 2
        for (int ktp = 0; ktp < 16; ++ktp) {
            uint32_t cb = (uint32_t)(ktp*64);
            uint32_t eh0[4], eh1[4], el0[4], el1[4];
            uint32_t oh0[4], oh1[4], ol0[4], ol1[4];
            ldm4(eh0, bh + lrowE + cb + lcs);
            ldm4(eh1, bh + lrowE + cb + 32 + lcs);
            ldm4(el0, bl + lrowE + cb + lcs);
            ldm4(el1, bl + lrowE + cb + 32 + lcs);
            ldm4(oh0, bh + lrowO + cb + lcs);
            ldm4(oh1, bh + lrowO + cb + 32 + lcs);
            ldm4(ol0, bl + lrowO + cb + lcs);
            ldm4(ol1, bl + lrowO + cb + 32 + lcs);
            #pragma unroll
            for (int nt = 0; nt < 4; ++nt) {
                uint4 bv = *(const uint4*)(Apk +
                    ((((size_t)(wid*4 + nt)*16 + ktp)*32 + lane) << 3));
                mmaf16(aE[nt], eh0, bv.x, bv.y);
                mmaf16(aE[nt], eh1, bv.z, bv.w);
                mmaf16(aE[nt], el0, bv.x, bv.y);
                mmaf16(aE[nt], el1, bv.z, bv.w);
                mmaf16(aO[nt], oh0, bv.x, bv.y);
                mmaf16(aO[nt], oh1, bv.z, bv.w);
                mmaf16(aO[nt], ol0, bv.x, bv.y);
                mmaf16(aO[nt], ol1, bv.z, bv.w);
            }
        }

        char* nb = sm + (buf ^ 1)*EOBUF;
        bool wr  = (s >= s0);
        bool wrE3 = wr && (s <= 2046);   // states3 even (t=2s+2 <= 4095)
        bool wrO = wr && (s <= 2046);
        #pragma unroll
        for (int nt = 0; nt < 4; ++nt) {
            int n = nbase + nt*8 + tig*2;
            #pragma unroll
            for (int half = 0; half < 2; ++half) {
                int b = gid + half*8;
                float vE0 = aE[nt][half*2], vE1 = aE[nt][half*2+1];
                float vO0 = aO[nt][half*2], vO1 = aO[nt][half*2+1];
                __half hE0 = __float2half(vE0), hE1 = __float2half(vE1);
                __half hO0 = __float2half(vO0), hO1 = __float2half(vO1);
                __half lE0 = __float2half(vE0 - __half2float(hE0));
                __half lE1 = __float2half(vE1 - __half2float(hE1));
                __half lO0 = __float2half(vO0 - __half2float(hO0));
                __half lO1 = __float2half(vO1 - __half2float(hO1));
                *(__half2*)(nb + b*XP + n*2)              = __halves2half2(hE0, hE1);
                *(__half2*)(nb + (16+b)*XP + n*2)         = __halves2half2(hO0, hO1);
                *(__half2*)(nb + SEC + b*XP + n*2)        = __halves2half2(lE0, lE1);
                *(__half2*)(nb + SEC + (16+b)*XP + n*2)   = __halves2half2(lO0, lO1);
                if (wr)
                    *(float2*)(states + ((size_t)b*(SEQL+1) + 2*s + 2)*DX + n) = make_float2(vE0, vE1);
                if (wrO)
                    *(float2*)(states + ((size_t)b*(SEQL+1) + 2*s + 3)*DX + n) = make_float2(vO0, vO1);
                // fused states3 A-side split (pre-states rows t)
                if (wrE3) wpairA(c_big1 + ((size_t)b*SEQL + 2*s + 2)*1536, 0, n, DX, vE0, vE1);
                if (wrO)  wpairA(c_big1 + ((size_t)b*SEQL + 2*s + 3)*1536, 0, n, DX, vO0, vO1);
            }
        }
        __syncthreads();
        buf ^= 1;
    }
}

// ---------------- host ----------------
static void* symaddr(const void* sym) {
    void* p = nullptr;
    cudaGetSymbolAddress(&p, sym);
    return p;
}

struct TcArgs {
    const float* Dm = nullptr; float* Cp = nullptr;
    __nv_bfloat16* outA = nullptr; __nv_bfloat16* outBr = nullptr; __nv_bfloat16* outBt = nullptr;
    int ldd = 0, ldc = 0, amode = 0; float alpha = 1.f, beta = 0.f;
    int tridx = 0, trslot = -1, frobslot = -1;
};

static void TCG(const __nv_bfloat16* A3, const __nv_bfloat16* B3,
                int M, int N, int K3, const TcArgs& a)
{
    if (M >= 1024) {
        dim3 g(N/128, M/128);
        tc_gemm<4,4><<<g, 256, 98304>>>(A3, B3, a.Dm, a.Cp, a.outA, a.outBr, a.outBt,
                                        K3, N, M, a.ldd, a.ldc, a.amode, a.alpha, a.beta,
                                        a.tridx, a.trslot, a.frobslot);
    } else {
        dim3 g(N/64, M/64);
        tc_gemm<2,2><<<g, 128, 49152>>>(A3, B3, a.Dm, a.Cp, a.outA, a.outBr, a.outBt,
                                        K3, N, M, a.ldd, a.ldc, a.amode, a.alpha, a.beta,
                                        a.tridx, a.trslot, a.frobslot);
    }
}

extern "C" void kernel_launch(void* const* d_in, const int* in_sizes, int n_in,
                              void* d_out, int out_size)
{
    const float *u = nullptr, *state = nullptr, *S = nullptr, *Kraw = nullptr;
    for (int i = 0; i < n_in; ++i) {
        long long sz = in_sizes[i];
        if      (sz == (long long)NB*SEQL*DU) u     = (const float*)d_in[i];
        else if (sz == (long long)NB*DX)      state = (const float*)d_in[i];
        else if (sz == (long long)DX*DX)      S     = (const float*)d_in[i];
        else if (sz == (long long)DK*DK)      Kraw  = (const float*)d_in[i];
    }
    float* out = (float*)d_out;

    cudaFuncSetAttribute((const void*)tc_gemm<4,4>, cudaFuncAttributeMaxDynamicSharedMemorySize, 98304);
    cudaFuncSetAttribute((const void*)tc_gemm<2,2>, cudaFuncAttributeMaxDynamicSharedMemorySize, 49152);
    cudaFuncSetAttribute((const void*)scan_eo_kernel, cudaFuncAttributeMaxDynamicSharedMemorySize, EO_SMEM);

    float* pXa   = (float*)symaddr(g_Xa);
    float* pXb   = (float*)symaddr(g_Xb);
    float* pAmat = (float*)symaddr(g_Amat);
    float* pA2   = (float*)symaddr(g_A2);
    float* pG    = (float*)symaddr(g_G);
    float* pBm   = (float*)symaddr(g_Bm);
    float* pBu   = (float*)symaddr(g_Bu);
    float* pX1   = (float*)symaddr(g_X1);
    float* pFall = (float*)symaddr(g_states_fallback);
    __half* pApk = (__half*)symaddr(g_Apk);

    __nv_bfloat16* pKT  = (__nv_bfloat16*)symaddr(c_kt);
    __nv_bfloat16* pM   = (__nv_bfloat16*)symaddr(c_m);
    __nv_bfloat16* pKT2 = (__nv_bfloat16*)symaddr(c_kt2);
    __nv_bfloat16* pM2  = (__nv_bfloat16*)symaddr(c_m2);
    __nv_bfloat16* pS   = (__nv_bfloat16*)symaddr(c_s);
    __nv_bfloat16* pST  = (__nv_bfloat16*)symaddr(c_st);
    __nv_bfloat16* pXR[2] = {(__nv_bfloat16*)symaddr(c_xr0), (__nv_bfloat16*)symaddr(c_xr1)};
    __nv_bfloat16* pXT[2] = {(__nv_bfloat16*)symaddr(c_xt0), (__nv_bfloat16*)symaddr(c_xt1)};
    __nv_bfloat16* pPT  = (__nv_bfloat16*)symaddr(c_pt);
    __nv_bfloat16* pK11 = (__nv_bfloat16*)symaddr(c_k11);
    __nv_bfloat16* pK12 = (__nv_bfloat16*)symaddr(c_k12);
    __nv_bfloat16* pK21 = (__nv_bfloat16*)symaddr(c_k21);
    __nv_bfloat16* pT1T = (__nv_bfloat16*)symaddr(c_t1t);
    __nv_bfloat16* pAR  = (__nv_bfloat16*)symaddr(c_ar);
    __nv_bfloat16* pAT  = (__nv_bfloat16*)symaddr(c_at);
    __nv_bfloat16* pBMT = (__nv_bfloat16*)symaddr(c_bmt);
    __nv_bfloat16* pGB  = (__nv_bfloat16*)symaddr(c_gb);
    __nv_bfloat16* pCW  = (__nv_bfloat16*)symaddr(c_cw);
    __nv_bfloat16* pDW  = (__nv_bfloat16*)symaddr(c_dw);
    __nv_bfloat16* pBig1 = (__nv_bfloat16*)symaddr(c_big1);
    __nv_bfloat16* pBig2 = (__nv_bfloat16*)symaddr(c_big2);

    float* states = ((long long)out_size >= (long long)OUT_ELEMS + (long long)ST_ELEMS)
                    ? (out + OUT_ELEMS) : pFall;

    // 1. prep: all input splits + X1 = 2I - S + g_tr reset
    prep_kernel<<<(1114112 + 255)/256, 256>>>(S, Kraw);

    // 2. sigma chain: M0 = K^T K (trace->0), 7 squarings (trace i+1), final frob
    {
        TcArgs a; a.outA = pKT2; a.outBr = pM2; a.trslot = 0;
        TCG(pKT, pM, DK, DK, 3*DK, a);                      // M0; splits in odd pair
    }
    __nv_bfloat16* sqA[2] = {pKT, pKT2};
    __nv_bfloat16* sqB[2] = {pM,  pM2};
    for (int i = 0; i < 7; ++i) {
        int p = (i + 1) & 1;                                // M_i splits live in pair p
        TcArgs a; a.amode = 1; a.tridx = i;
        a.outA = sqA[p ^ 1]; a.outBr = sqB[p ^ 1]; a.trslot = i + 1;
        TCG(sqA[p], sqB[p], DK, DK, 3*DK, a);               // M_{i+1}
    }
    {
        int p = 0;                                          // M_7 splits in pair (7+1)&1 = 0
        TcArgs a; a.amode = 1; a.tridx = 7; a.frobslot = 8;
        TCG(sqA[p], sqB[p], DK, DK, 3*DK, a);               // frob(M_8) only
    }
    finalize_kernel<<<1,1>>>();

    // 3. Newton-Schulz (X1 = 2I - S precomputed): 3 iterations
    float* Xc = pXa; float* Xn = pXb;
    int pp = 0;
    for (int it = 0; it < 3; ++it) {
        { TcArgs a; a.outBt = pPT;
          TCG(pS, pXT[pp], DX, DX, 1536, a); }              // P = S@Xc -> P^T split only
        { TcArgs a; a.Dm = Xc; a.Cp = Xn; a.ldd = DX; a.ldc = DX;
          a.alpha = -1.f; a.beta = 2.f;
          a.outA = pXR[pp ^ 1]; a.outBt = pXT[pp ^ 1];
          TCG(pXR[pp], pPT, DX, DX, 1536, a); }             // Xn = 2Xc - Xc@P
        float* t = Xc; Xc = Xn; Xn = t; pp ^= 1;
    }
    __nv_bfloat16* pSinvR = pXR[pp];                        // Sinv rows A-side

    // 4. assemble A, Bm, Cw, Dw (kscale fused)
    { TcArgs a; a.amode = 2; a.outBt = pT1T;
      TCG(pK11, pST, DX, DX, 1536, a); }                    // T1 = ks*K11@S -> T1^T
    { TcArgs a; a.Cp = pAmat; a.ldc = DX; a.outA = pAR; a.outBt = pAT;
      TCG(pSinvR, pT1T, DX, DX, 1536, a); }                 // A = Sinv@T1
    { TcArgs a; a.amode = 2; a.Cp = pBm; a.ldc = DU; a.outBt = pBMT;
      TCG(pSinvR, pK12, DX, DU, 1536, a); }                 // Bm = ks*Sinv@K12
    { TcArgs a; a.amode = 2; a.outBr = pCW;
      TCG(pK21, pST, DOUT, DX, 1536, a); }                  // Cw = ks*K21@S
    dw_kernel<<<(DOUT*DU)/256, 256>>>(Kraw);

    // 5. A^2 and G = A@Bm
    { TcArgs a; a.Cp = pA2; a.ldc = DX;
      TCG(pAR, pAT, DX, DX, 1536, a); }                     // A2
    pack_frag_kernel<<<(DX*DX)/256, 256>>>(pA2);
    { TcArgs a; a.Cp = pG; a.ldc = DU;
      TCG(pAR, pBMT, DX, DU, 1536, a); }                    // G
    gb_kernel<<<(DX*DX)/256, 256>>>();

    // 6. c = u2 @ [G|Bm]^T
    u23_kernel<<<(NB*SEQL*DX)/256, 256>>>(u);
    { TcArgs a; a.Cp = pBu; a.ldc = DX;
      TCG(pBig1, pGB, NB*SEQL, DX, 1536, a); }

    // 7. states rows 0,1 + even/odd scan (fused states3 split)
    state0_kernel<<<(NB*DX)/256, 256>>>(state, states);
    x1_kernel<<<NB, 512>>>(state, u, states);
    scan_eo_kernel<<<EO_NCH, 512, EO_SMEM>>>(pBu, pApk, state, pX1, states);

    // 8. output = pre_states @ Cw^T + u @ Dw^T
    { TcArgs a; a.Cp = out; a.ldc = DOUT;
      TCG(pBig1, pCW, NB*SEQL, DOUT, 1536, a); }
    { TcArgs a; a.Dm = out; a.Cp = out; a.ldd = DOUT; a.ldc = DOUT; a.beta = 1.f;
      TCG(pBig2, pDW, NB*SEQL, DOUT, 768, a); }
}